// round 2
// baseline (speedup 1.0000x reference)
#include <cuda_runtime.h>
#include <stdint.h>
#include <math.h>

// Problem constants
#define BB 8
#define NN 100000
#define MM 2048
#define KK 32
#define DD 128
#define IC 132            // D + 4 input channels to W1
#define EPSV 1e-5f

#define XS_STRIDE 136     // floats per x row (132 padded to 136 for alignment)
#define HS_STRIDE 128     // floats per hidden row

// FiLM scratch: gamma|beta per batch, [B][2*D]
__device__ float g_film[BB * 2 * DD];
// Mask dtype flag: 1 = uint8 layout, 0 = int32 layout
__device__ int g_mask_is_u8;

__device__ __forceinline__ float silu_f(float v) {
    return v * (1.0f / (1.0f + __expf(-v)));
}

// ---------------------------------------------------------------------------
// Mask dtype detection: if stored as int32 0/1, every 32-bit word is in {0,1}.
// If stored as uint8 0/1 random, words >1 occur with overwhelming probability.
// ---------------------------------------------------------------------------
__global__ void detect_mask_kernel(const unsigned* __restrict__ m) {
    __shared__ int found;
    if (threadIdx.x == 0) found = 0;
    __syncthreads();
    bool big = false;
    for (int i = threadIdx.x; i < 2048; i += blockDim.x)
        if (m[i] > 1u) big = true;
    if (big) atomicOr(&found, 1);
    __syncthreads();
    if (threadIdx.x == 0) g_mask_is_u8 = found;
}

// ---------------------------------------------------------------------------
// FiLM precompute: g_film[b][j] = task_emb[b] @ Wf[:, j] + bf[j],  j in [0,256)
// ---------------------------------------------------------------------------
__global__ void film_kernel(const float* __restrict__ task_emb,
                            const float* __restrict__ Wf,
                            const float* __restrict__ bf) {
    int b = blockIdx.x;
    int j = threadIdx.x;              // 0..255
    float acc = bf[j];
    const float* te = task_emb + b * DD;
#pragma unroll 8
    for (int d = 0; d < DD; ++d)
        acc += te[d] * Wf[d * (2 * DD) + j];
    g_film[b * (2 * DD) + j] = acc;
}

// ---------------------------------------------------------------------------
// Main kernel: persistent CTAs, 512 threads, 2 supernodes per iteration.
// ---------------------------------------------------------------------------
#define SMEM_FLOATS (IC*DD + DD*DD + 2*KK*XS_STRIDE + 2*KK*HS_STRIDE + 2*8*DD + 16)
#define SMEM_BYTES  (SMEM_FLOATS*4 + 2*(KK+1)*4 + 64)

extern __shared__ float smem[];

__global__ __launch_bounds__(512, 1)
void msg_kernel(const float* __restrict__ point_feat,
                const float* __restrict__ point_xyz,
                const float* __restrict__ sup_xyz,
                const int*   __restrict__ nidx,
                const void*  __restrict__ nmask,
                const float* __restrict__ init_feat,
                const float* __restrict__ W1, const float* __restrict__ b1,
                const float* __restrict__ W2, const float* __restrict__ b2,
                const float* __restrict__ ln_g, const float* __restrict__ ln_b,
                float* __restrict__ out)
{
    float* W1s  = smem;                           // 132*128
    float* W2s  = W1s + IC * DD;                  // 128*128
    float* xs   = W2s + DD * DD;                  // 2 * 32 * 136
    float* hs   = xs  + 2 * KK * XS_STRIDE;       // 2 * 32 * 128
    float* part = hs  + 2 * KK * HS_STRIDE;       // 2 * 8 * 128
    float* red  = part + 2 * 8 * DD;              // 2 * 4 * 2
    int*   cidx = (int*)(red + 16);               // 2 * 32
    int*   Vsh  = (int*)(cidx + 2 * KK);          // 2

    const int tid = threadIdx.x;
    const int mask_u8 = g_mask_is_u8;

    // Stage weights once per CTA (sync happens inside the loop before use)
    for (int i = tid; i < (IC * DD) / 4; i += 512)
        ((float4*)W1s)[i] = ((const float4*)W1)[i];
    for (int i = tid; i < (DD * DD) / 4; i += 512)
        ((float4*)W2s)[i] = ((const float4*)W2)[i];

    const int half = tid >> 8;          // which supernode of the pair
    const int tid2 = tid & 255;
    const int cx   = tid2 & 31;         // column group: cols 4*cx..4*cx+3
    const int ry   = tid2 >> 5;         // row group (warp): rows 4*ry..4*ry+3

    float* xsh   = xs   + half * KK * XS_STRIDE;
    float* hsh   = hs   + half * KK * HS_STRIDE;
    float* parth = part + half * 8 * DD;
    float* redh  = red  + half * 8;
    int*   cidxh = cidx + half * KK;

    const float4 b1v = *(const float4*)(b1 + 4 * cx);
    const float4 b2v = *(const float4*)(b2 + 4 * cx);
    const float4* __restrict__ W1q = (const float4*)W1s;
    const float4* __restrict__ W2q = (const float4*)W2s;

    const int total_pairs = (BB * MM) / 2;

    for (int pair = blockIdx.x; pair < total_pairs; pair += gridDim.x) {
        const int s = pair * 2 + half;            // supernode global index
        const int b = s / MM;

        // ---- compact valid neighbors (warp 0 of each half) ----
        if (tid2 < 32) {
            const int k = tid2;
            const long base = (long)s * KK + k;
            const int nid = nidx[base];
            bool mk;
            if (mask_u8) mk = ((const uint8_t*)nmask)[base] != 0;
            else         mk = ((const int*)nmask)[base] != 0;
            const unsigned bal = __ballot_sync(0xffffffffu, mk);
            const int pos = __popc(bal & ((1u << k) - 1u));
            if (mk) cidxh[pos] = nid;
            if (k == 0) Vsh[half] = __popc(bal);
        }
        __syncthreads();
        const int V = Vsh[half];

        // ---- gather x = [feat(128) | rel(3) | dist(1)] into SMEM ----
        {
            const float sx = sup_xyz[s * 3 + 0];
            const float sy = sup_xyz[s * 3 + 1];
            const float sz = sup_xyz[s * 3 + 2];
            const float* pf = point_feat + (size_t)b * NN * DD;
            const float* px = point_xyz  + (size_t)b * NN * 3;
            for (int r = ry; r < KK; r += 8) {
                float4 v = make_float4(0.f, 0.f, 0.f, 0.f);
                int nid = 0;
                if (r < V) {
                    nid = cidxh[r];
                    v = *(const float4*)(pf + (size_t)nid * DD + 4 * cx);
                }
                *(float4*)(xsh + r * XS_STRIDE + 4 * cx) = v;
                if (cx == 0) {
                    float rx = 0.f, ryv = 0.f, rz = 0.f, dd = 0.f;
                    if (r < V) {
                        rx  = px[nid * 3 + 0] - sx;
                        ryv = px[nid * 3 + 1] - sy;
                        rz  = px[nid * 3 + 2] - sz;
                        dd  = sqrtf(rx * rx + ryv * ryv + rz * rz);
                    }
                    xsh[r * XS_STRIDE + 128] = rx;
                    xsh[r * XS_STRIDE + 129] = ryv;
                    xsh[r * XS_STRIDE + 130] = rz;
                    xsh[r * XS_STRIDE + 131] = dd;
                }
            }
        }
        __syncthreads();

        const int r0 = 4 * ry;
        float4 psum = make_float4(0.f, 0.f, 0.f, 0.f);

        if (r0 < V) {   // whole-warp skip of fully-masked row tiles
            // ---- GEMM1: hidden = silu(x @ W1 + b1), 4x4 tile per thread ----
            float a[4][4];
#pragma unroll
            for (int j = 0; j < 4; ++j) {
                a[j][0] = b1v.x; a[j][1] = b1v.y; a[j][2] = b1v.z; a[j][3] = b1v.w;
            }
            const float4* xr0 = (const float4*)(xsh + (r0 + 0) * XS_STRIDE);
            const float4* xr1 = (const float4*)(xsh + (r0 + 1) * XS_STRIDE);
            const float4* xr2 = (const float4*)(xsh + (r0 + 2) * XS_STRIDE);
            const float4* xr3 = (const float4*)(xsh + (r0 + 3) * XS_STRIDE);
            for (int i4 = 0; i4 < IC / 4; ++i4) {
                float xv[4][4];
                float4 t;
                t = xr0[i4]; xv[0][0]=t.x; xv[0][1]=t.y; xv[0][2]=t.z; xv[0][3]=t.w;
                t = xr1[i4]; xv[1][0]=t.x; xv[1][1]=t.y; xv[1][2]=t.z; xv[1][3]=t.w;
                t = xr2[i4]; xv[2][0]=t.x; xv[2][1]=t.y; xv[2][2]=t.z; xv[2][3]=t.w;
                t = xr3[i4]; xv[3][0]=t.x; xv[3][1]=t.y; xv[3][2]=t.z; xv[3][3]=t.w;
#pragma unroll
                for (int tt = 0; tt < 4; ++tt) {
                    const float4 w = W1q[(i4 * 4 + tt) * 32 + cx];
#pragma unroll
                    for (int j = 0; j < 4; ++j) {
                        a[j][0] += xv[j][tt] * w.x;
                        a[j][1] += xv[j][tt] * w.y;
                        a[j][2] += xv[j][tt] * w.z;
                        a[j][3] += xv[j][tt] * w.w;
                    }
                }
            }
            // silu + stage hidden tile (consumed only within this warp)
#pragma unroll
            for (int j = 0; j < 4; ++j) {
                float4 hv;
                hv.x = silu_f(a[j][0]); hv.y = silu_f(a[j][1]);
                hv.z = silu_f(a[j][2]); hv.w = silu_f(a[j][3]);
                *(float4*)(hsh + (r0 + j) * HS_STRIDE + 4 * cx) = hv;
            }
            __syncwarp();

            // ---- GEMM2: msg = hidden @ W2 + b2 ----
            float a2[4][4];
#pragma unroll
            for (int j = 0; j < 4; ++j) {
                a2[j][0] = b2v.x; a2[j][1] = b2v.y; a2[j][2] = b2v.z; a2[j][3] = b2v.w;
            }
            const float4* hr0 = (const float4*)(hsh + (r0 + 0) * HS_STRIDE);
            const float4* hr1 = (const float4*)(hsh + (r0 + 1) * HS_STRIDE);
            const float4* hr2 = (const float4*)(hsh + (r0 + 2) * HS_STRIDE);
            const float4* hr3 = (const float4*)(hsh + (r0 + 3) * HS_STRIDE);
            for (int i4 = 0; i4 < DD / 4; ++i4) {
                float xv[4][4];
                float4 t;
                t = hr0[i4]; xv[0][0]=t.x; xv[0][1]=t.y; xv[0][2]=t.z; xv[0][3]=t.w;
                t = hr1[i4]; xv[1][0]=t.x; xv[1][1]=t.y; xv[1][2]=t.z; xv[1][3]=t.w;
                t = hr2[i4]; xv[2][0]=t.x; xv[2][1]=t.y; xv[2][2]=t.z; xv[2][3]=t.w;
                t = hr3[i4]; xv[3][0]=t.x; xv[3][1]=t.y; xv[3][2]=t.z; xv[3][3]=t.w;
#pragma unroll
                for (int tt = 0; tt < 4; ++tt) {
                    const float4 w = W2q[(i4 * 4 + tt) * 32 + cx];
#pragma unroll
                    for (int j = 0; j < 4; ++j) {
                        a2[j][0] += xv[j][tt] * w.x;
                        a2[j][1] += xv[j][tt] * w.y;
                        a2[j][2] += xv[j][tt] * w.z;
                        a2[j][3] += xv[j][tt] * w.w;
                    }
                }
            }
            // masked partial sum over this warp's rows
#pragma unroll
            for (int j = 0; j < 4; ++j) {
                if (r0 + j < V) {
                    psum.x += a2[j][0]; psum.y += a2[j][1];
                    psum.z += a2[j][2]; psum.w += a2[j][3];
                }
            }
        }
        // every thread writes its partial (zeros when warp skipped)
        *(float4*)(parth + ry * DD + 4 * cx) = psum;
        __syncthreads();

        // ---- epilogue: mean, FiLM, residual, LayerNorm (128 threads/half) ----
        float h = 0.f;
        const int c = tid2;
        if (tid2 < DD) {
            float agg = 0.f;
#pragma unroll
            for (int q = 0; q < 8; ++q) agg += parth[q * DD + c];
            agg /= fmaxf((float)V, 1.0f);
            const float gmm = g_film[b * (2 * DD) + c];
            const float bta = g_film[b * (2 * DD) + DD + c];
            agg = agg * (1.0f + gmm) + bta;
            h = init_feat[(size_t)s * DD + c] + agg;
            float sum = h, sq = h * h;
#pragma unroll
            for (int off = 16; off; off >>= 1) {
                sum += __shfl_xor_sync(0xffffffffu, sum, off);
                sq  += __shfl_xor_sync(0xffffffffu, sq,  off);
            }
            if ((tid2 & 31) == 0) {
                redh[(tid2 >> 5) * 2 + 0] = sum;
                redh[(tid2 >> 5) * 2 + 1] = sq;
            }
        }
        __syncthreads();
        if (tid2 < DD) {
            float sm = 0.f, sq = 0.f;
#pragma unroll
            for (int w = 0; w < 4; ++w) { sm += redh[w * 2]; sq += redh[w * 2 + 1]; }
            const float mu  = sm * (1.0f / DD);
            const float var = sq * (1.0f / DD) - mu * mu;
            const float y = (h - mu) * rsqrtf(var + EPSV) * ln_g[c] + ln_b[c];
            out[(size_t)s * DD + c] = y;
        }
        __syncthreads();   // protect V/cidx/xs before next iteration
    }
}

// ---------------------------------------------------------------------------
extern "C" void kernel_launch(void* const* d_in, const int* in_sizes, int n_in,
                              void* d_out, int out_size) {
    const float*   point_feat = (const float*)d_in[0];
    const float*   point_xyz  = (const float*)d_in[1];
    const float*   sup_xyz    = (const float*)d_in[2];
    const int*     nidx       = (const int*)d_in[3];
    const void*    nmask      = d_in[4];
    const float*   init_feat  = (const float*)d_in[5];
    const float*   task_emb   = (const float*)d_in[6];
    const float*   W1 = (const float*)d_in[7];
    const float*   b1 = (const float*)d_in[8];
    const float*   W2 = (const float*)d_in[9];
    const float*   b2 = (const float*)d_in[10];
    const float*   Wf = (const float*)d_in[11];
    const float*   bf = (const float*)d_in[12];
    const float*   lng = (const float*)d_in[13];
    const float*   lnb = (const float*)d_in[14];
    float* out = (float*)d_out;

    detect_mask_kernel<<<1, 256>>>((const unsigned*)nmask);
    film_kernel<<<BB, 256>>>(task_emb, Wf, bf);

    cudaFuncSetAttribute(msg_kernel, cudaFuncAttributeMaxDynamicSharedMemorySize,
                         SMEM_BYTES);
    int sms = 148;
    cudaDeviceGetAttribute(&sms, cudaDevAttrMultiProcessorCount, 0);

    msg_kernel<<<sms, 512, SMEM_BYTES>>>(point_feat, point_xyz, sup_xyz,
                                         nidx, nmask, init_feat,
                                         W1, b1, W2, b2, lng, lnb, out);
}

// round 5
// speedup vs baseline: 1.9049x; 1.9049x over previous
#include <cuda_runtime.h>
#include <stdint.h>
#include <math.h>

// Problem constants
#define BB 8
#define NN 100000
#define MM 2048
#define KK 32
#define DD 128
#define IC 132            // D + 4 input channels to W1
#define KP 136            // IC padded to multiple of 8
#define EPSV 1e-5f

#define STRX 140          // xs row stride (words)
#define STRH 132          // hs row stride
#define STRW 136          // W row stride

// FiLM scratch: gamma|beta per batch, [B][2*D]
__device__ float g_film[BB * 2 * DD];
// Mask dtype flag: 1 = uint8 layout, 0 = int32 layout
__device__ int g_mask_is_u8;

__device__ __forceinline__ float silu_f(float v) {
    return v * (1.0f / (1.0f + __expf(-v)));
}

__device__ __forceinline__ float to_tf32(float x) {
    unsigned u;
    asm("cvt.rna.tf32.f32 %0, %1;" : "=r"(u) : "f"(x));
    return __uint_as_float(u);
}

__device__ __forceinline__ void mma_tf32(float d[4],
                                         unsigned a0, unsigned a1,
                                         unsigned a2, unsigned a3,
                                         unsigned b0, unsigned b1) {
    asm volatile(
        "mma.sync.aligned.m16n8k8.row.col.f32.tf32.tf32.f32 "
        "{%0,%1,%2,%3}, {%4,%5,%6,%7}, {%8,%9}, {%0,%1,%2,%3};\n"
        : "+f"(d[0]), "+f"(d[1]), "+f"(d[2]), "+f"(d[3])
        : "r"(a0), "r"(a1), "r"(a2), "r"(a3), "r"(b0), "r"(b1));
}

// ---------------------------------------------------------------------------
// Mask dtype detection
// ---------------------------------------------------------------------------
__global__ void detect_mask_kernel(const unsigned* __restrict__ m) {
    __shared__ int found;
    if (threadIdx.x == 0) found = 0;
    __syncthreads();
    bool big = false;
    for (int i = threadIdx.x; i < 2048; i += blockDim.x)
        if (m[i] > 1u) big = true;
    if (big) atomicOr(&found, 1);
    __syncthreads();
    if (threadIdx.x == 0) g_mask_is_u8 = found;
}

// ---------------------------------------------------------------------------
// FiLM precompute
// ---------------------------------------------------------------------------
__global__ void film_kernel(const float* __restrict__ task_emb,
                            const float* __restrict__ Wf,
                            const float* __restrict__ bf) {
    int b = blockIdx.x;
    int j = threadIdx.x;              // 0..255
    float acc = bf[j];
    const float* te = task_emb + b * DD;
#pragma unroll 8
    for (int d = 0; d < DD; ++d)
        acc += te[d] * Wf[d * (2 * DD) + j];
    g_film[b * (2 * DD) + j] = acc;
}

// ---------------------------------------------------------------------------
// SMEM layout (floats)
// ---------------------------------------------------------------------------
#define W1S_F (KP * STRW)          // 136*136 = 18496
#define W2S_F (DD * STRW)          // 128*136 = 17408
#define XS_F  (2 * KK * STRX)      // 8960
#define HS_F  (2 * KK * STRH)      // 8448
#define PART_F (2 * 2 * DD)        // 512
#define RED_F  (2 * 8)             // 2 halves * 4 warps * 2 values
#define SMEM_FLOATS (W1S_F + W2S_F + XS_F + HS_F + PART_F + RED_F)
#define SMEM_BYTES  (SMEM_FLOATS * 4 + 2 * (KK + 1) * 4 + 64)

extern __shared__ float smem[];

__global__ __launch_bounds__(512, 1)
void msg_kernel(const float* __restrict__ point_feat,
                const float* __restrict__ point_xyz,
                const float* __restrict__ sup_xyz,
                const int*   __restrict__ nidx,
                const void*  __restrict__ nmask,
                const float* __restrict__ init_feat,
                const float* __restrict__ W1, const float* __restrict__ b1,
                const float* __restrict__ W2, const float* __restrict__ b2,
                const float* __restrict__ ln_g, const float* __restrict__ ln_b,
                float* __restrict__ out)
{
    float* W1s  = smem;
    float* W2s  = W1s + W1S_F;
    float* xs   = W2s + W2S_F;
    float* hs   = xs + XS_F;
    float* part = hs + HS_F;
    float* redm = part + PART_F;                  // 2 * 8, dedicated
    int*   cidx = (int*)(redm + RED_F);           // 2 * 32
    int*   Vsh  = (int*)(cidx + 2 * KK);          // 2

    const int tid = threadIdx.x;
    const int mask_u8 = g_mask_is_u8;

    // ---- stage weights (tf32-rounded, zero-padded) + zero hs ----
    for (int i = tid; i < KP * STRW; i += 512) {
        int r = i / STRW, c = i % STRW;
        float v = (r < IC && c < DD) ? to_tf32(W1[r * DD + c]) : 0.f;
        W1s[i] = v;
    }
    for (int i = tid; i < DD * STRW; i += 512) {
        int r = i / STRW, c = i % STRW;
        float v = (c < DD) ? to_tf32(W2[r * DD + c]) : 0.f;
        W2s[i] = v;
    }
    for (int i = tid; i < HS_F; i += 512) hs[i] = 0.f;
    __syncthreads();

    const int half = tid >> 8;
    const int tid2 = tid & 255;
    const int w    = tid2 >> 5;          // warp in half: 0..7
    const int lane = tid2 & 31;
    const int g    = lane >> 2;          // groupID 0..7
    const int q    = lane & 3;           // threadID_in_group
    const int mt   = w & 1;              // m16 tile (rows mt*16..)
    const int wn   = w >> 1;             // 32-col block (0..3)
    const int R    = mt * 16;
    const int barid = half + 1;

    float* xsh   = xs   + half * KK * STRX;
    float* hsh   = hs   + half * KK * STRH;
    float* parth = part + half * 2 * DD;
    float* redh  = redm + half * 8;
    int*   cidxh = cidx + half * KK;

    // per-tile biases (cols c0, c0+1)
    float bi1[4][2], bi2[4][2];
#pragma unroll
    for (int t = 0; t < 4; ++t) {
        int c0 = wn * 32 + t * 8 + 2 * q;
        bi1[t][0] = b1[c0]; bi1[t][1] = b1[c0 + 1];
        bi2[t][0] = b2[c0]; bi2[t][1] = b2[c0 + 1];
    }

    const int total_pairs = (BB * MM) / 2;

    for (int pair = blockIdx.x; pair < total_pairs; pair += gridDim.x) {
        const int s = pair * 2 + half;
        const int b = s / MM;

        // ---- compact valid neighbors (warp 0 of each half) ----
        if (tid2 < 32) {
            const int k = tid2;
            const long base = (long)s * KK + k;
            const int nid = nidx[base];
            bool mk;
            if (mask_u8) mk = ((const uint8_t*)nmask)[base] != 0;
            else         mk = ((const int*)nmask)[base] != 0;
            const unsigned bal = __ballot_sync(0xffffffffu, mk);
            const int pos = __popc(bal & ((1u << k) - 1u));
            if (mk) cidxh[pos] = nid;
            if (k == 0) Vsh[half] = __popc(bal);
        }
        asm volatile("bar.sync %0, %1;" :: "r"(barid), "r"(256) : "memory");
        const int V = Vsh[half];

        // ---- gather x = [feat | rel | dist] (tf32-rounded) ----
        {
            const float sx = sup_xyz[s * 3 + 0];
            const float sy = sup_xyz[s * 3 + 1];
            const float sz = sup_xyz[s * 3 + 2];
            const float* pf = point_feat + (size_t)b * NN * DD;
            const float* px = point_xyz  + (size_t)b * NN * 3;
            const int cx = lane;   // 0..31, one float4 per lane
            for (int r = w; r < KK; r += 8) {
                float4 v = make_float4(0.f, 0.f, 0.f, 0.f);
                int nid = 0;
                if (r < V) {
                    nid = cidxh[r];
                    float4 t = *(const float4*)(pf + (size_t)nid * DD + 4 * cx);
                    v.x = to_tf32(t.x); v.y = to_tf32(t.y);
                    v.z = to_tf32(t.z); v.w = to_tf32(t.w);
                }
                *(float4*)(xsh + r * STRX + 4 * cx) = v;
                if (cx == 0) {
                    float rx = 0.f, ryv = 0.f, rz = 0.f, dd = 0.f;
                    if (r < V) {
                        rx  = px[nid * 3 + 0] - sx;
                        ryv = px[nid * 3 + 1] - sy;
                        rz  = px[nid * 3 + 2] - sz;
                        dd  = sqrtf(rx * rx + ryv * ryv + rz * rz);
                    }
                    xsh[r * STRX + 128] = to_tf32(rx);
                    xsh[r * STRX + 129] = to_tf32(ryv);
                    xsh[r * STRX + 130] = to_tf32(rz);
                    xsh[r * STRX + 131] = to_tf32(dd);
                } else if (cx == 1) {
                    // zero K-padding cols 132..135
                    *(float4*)(xsh + r * STRX + 132) = make_float4(0.f, 0.f, 0.f, 0.f);
                }
            }
        }
        asm volatile("bar.sync %0, %1;" :: "r"(barid), "r"(256) : "memory");

        const bool skip = (R >= V);
        float d[4][4];

        if (!skip) {
            // ---- GEMM1: hidden = silu(x @ W1 + b1) via tf32 MMA ----
#pragma unroll
            for (int t = 0; t < 4; ++t) {
                d[t][0] = bi1[t][0]; d[t][1] = bi1[t][1];
                d[t][2] = bi1[t][0]; d[t][3] = bi1[t][1];
            }
            const unsigned* xa = (const unsigned*)(xsh + (R + g) * STRX + q);
            const unsigned* bp = (const unsigned*)(W1s + q * STRW + wn * 32 + g);
#pragma unroll
            for (int kk = 0; kk < KP / 8; ++kk) {
                unsigned a0 = xa[kk * 8];
                unsigned a1 = xa[8 * STRX + kk * 8];
                unsigned a2 = xa[kk * 8 + 4];
                unsigned a3 = xa[8 * STRX + kk * 8 + 4];
#pragma unroll
                for (int t = 0; t < 4; ++t) {
                    unsigned b0 = bp[kk * 8 * STRW + t * 8];
                    unsigned b1r = bp[(kk * 8 + 4) * STRW + t * 8];
                    mma_tf32(d[t], a0, a1, a2, a3, b0, b1r);
                }
            }
            // silu + tf32 round + store hidden
#pragma unroll
            for (int t = 0; t < 4; ++t) {
                int c0 = wn * 32 + t * 8 + 2 * q;
                float2 lo = make_float2(to_tf32(silu_f(d[t][0])),
                                        to_tf32(silu_f(d[t][1])));
                float2 hi = make_float2(to_tf32(silu_f(d[t][2])),
                                        to_tf32(silu_f(d[t][3])));
                *(float2*)(hsh + (R + g) * STRH + c0) = lo;
                *(float2*)(hsh + (R + g + 8) * STRH + c0) = hi;
            }
        }
        // all hidden cols must be visible before GEMM2 A-reads
        asm volatile("bar.sync %0, %1;" :: "r"(barid), "r"(256) : "memory");

        float sums[4][2];
        if (!skip) {
            // ---- GEMM2: msg = hidden @ W2 + b2 ----
#pragma unroll
            for (int t = 0; t < 4; ++t) {
                d[t][0] = bi2[t][0]; d[t][1] = bi2[t][1];
                d[t][2] = bi2[t][0]; d[t][3] = bi2[t][1];
            }
            const unsigned* ha = (const unsigned*)(hsh + (R + g) * STRH + q);
            const unsigned* bp = (const unsigned*)(W2s + q * STRW + wn * 32 + g);
#pragma unroll
            for (int kk = 0; kk < DD / 8; ++kk) {
                unsigned a0 = ha[kk * 8];
                unsigned a1 = ha[8 * STRH + kk * 8];
                unsigned a2 = ha[kk * 8 + 4];
                unsigned a3 = ha[8 * STRH + kk * 8 + 4];
#pragma unroll
                for (int t = 0; t < 4; ++t) {
                    unsigned b0 = bp[kk * 8 * STRW + t * 8];
                    unsigned b1r = bp[(kk * 8 + 4) * STRW + t * 8];
                    mma_tf32(d[t], a0, a1, a2, a3, b0, b1r);
                }
            }
            // masked row sums (selects, NaN-safe)
            const bool vlo = (R + g) < V;
            const bool vhi = (R + g + 8) < V;
#pragma unroll
            for (int t = 0; t < 4; ++t) {
                sums[t][0] = (vlo ? d[t][0] : 0.f) + (vhi ? d[t][2] : 0.f);
                sums[t][1] = (vlo ? d[t][1] : 0.f) + (vhi ? d[t][3] : 0.f);
            }
        } else {
#pragma unroll
            for (int t = 0; t < 4; ++t) { sums[t][0] = 0.f; sums[t][1] = 0.f; }
        }
        // reduce over row groups (lane bits 2..4)
#pragma unroll
        for (int t = 0; t < 4; ++t) {
#pragma unroll
            for (int off = 4; off <= 16; off <<= 1) {
                sums[t][0] += __shfl_xor_sync(0xffffffffu, sums[t][0], off);
                sums[t][1] += __shfl_xor_sync(0xffffffffu, sums[t][1], off);
            }
        }
        if (lane < 4) {
#pragma unroll
            for (int t = 0; t < 4; ++t) {
                int c0 = wn * 32 + t * 8 + 2 * q;
                parth[mt * DD + c0]     = sums[t][0];
                parth[mt * DD + c0 + 1] = sums[t][1];
            }
        }
        asm volatile("bar.sync %0, %1;" :: "r"(barid), "r"(256) : "memory");

        // ---- epilogue: mean, FiLM, residual, LayerNorm ----
        float h = 0.f;
        if (tid2 < DD) {
            const int c = tid2;
            float agg = (parth[c] + parth[DD + c]) / fmaxf((float)V, 1.0f);
            const float gmm = g_film[b * (2 * DD) + c];
            const float bta = g_film[b * (2 * DD) + DD + c];
            agg = agg * (1.0f + gmm) + bta;
            h = init_feat[(size_t)s * DD + c] + agg;
            float sum = h, sq = h * h;
#pragma unroll
            for (int off = 16; off; off >>= 1) {
                sum += __shfl_xor_sync(0xffffffffu, sum, off);
                sq  += __shfl_xor_sync(0xffffffffu, sq,  off);
            }
            if ((tid2 & 31) == 0) {
                redh[(tid2 >> 5) * 2 + 0] = sum;   // dedicated scratch, no alias
                redh[(tid2 >> 5) * 2 + 1] = sq;
            }
        }
        asm volatile("bar.sync %0, %1;" :: "r"(barid), "r"(256) : "memory");
        if (tid2 < DD) {
            const int c = tid2;
            float sm = 0.f, sq = 0.f;
#pragma unroll
            for (int ww = 0; ww < 4; ++ww) {
                sm += redh[ww * 2];
                sq += redh[ww * 2 + 1];
            }
            const float mu  = sm * (1.0f / DD);
            const float var = sq * (1.0f / DD) - mu * mu;
            const float y = (h - mu) * rsqrtf(var + EPSV) * ln_g[c] + ln_b[c];
            out[(size_t)s * DD + c] = y;
        }
        asm volatile("bar.sync %0, %1;" :: "r"(barid), "r"(256) : "memory");
    }
}

// ---------------------------------------------------------------------------
extern "C" void kernel_launch(void* const* d_in, const int* in_sizes, int n_in,
                              void* d_out, int out_size) {
    const float*   point_feat = (const float*)d_in[0];
    const float*   point_xyz  = (const float*)d_in[1];
    const float*   sup_xyz    = (const float*)d_in[2];
    const int*     nidx       = (const int*)d_in[3];
    const void*    nmask      = d_in[4];
    const float*   init_feat  = (const float*)d_in[5];
    const float*   task_emb   = (const float*)d_in[6];
    const float*   W1 = (const float*)d_in[7];
    const float*   b1 = (const float*)d_in[8];
    const float*   W2 = (const float*)d_in[9];
    const float*   b2 = (const float*)d_in[10];
    const float*   Wf = (const float*)d_in[11];
    const float*   bf = (const float*)d_in[12];
    const float*   lng = (const float*)d_in[13];
    const float*   lnb = (const float*)d_in[14];
    float* out = (float*)d_out;

    detect_mask_kernel<<<1, 256>>>((const unsigned*)nmask);
    film_kernel<<<BB, 256>>>(task_emb, Wf, bf);

    cudaFuncSetAttribute(msg_kernel, cudaFuncAttributeMaxDynamicSharedMemorySize,
                         SMEM_BYTES);
    int sms = 148;
    cudaDeviceGetAttribute(&sms, cudaDevAttrMultiProcessorCount, 0);

    msg_kernel<<<sms, 512, SMEM_BYTES>>>(point_feat, point_xyz, sup_xyz,
                                         nidx, nmask, init_feat,
                                         W1, b1, W2, b2, lng, lnb, out);
}

// round 6
// speedup vs baseline: 2.2936x; 1.2040x over previous
#include <cuda_runtime.h>
#include <cuda_bf16.h>
#include <stdint.h>
#include <math.h>

// Problem constants
#define BB 8
#define NN 100000
#define MM 2048
#define KK 32
#define DD 128
#define IC 132
#define EPSV 1e-5f

// word strides (32-bit words; each word = 2 bf16 along K)
#define STRX 76      // xs row stride: 76%32=12 -> g*12+q bijective
#define STRH 68      // hs row stride: 68%32=4  -> g*4+q bijective
#define STRW1 76
#define STRW2 68

// SMEM word-offset layout
#define OFF_FILM 0                   // 2048 floats
#define OFF_PART 2048                // 4*128 floats
#define OFF_RED  2560                // 4*8 floats
#define OFF_FLAG 2592                // 1 int
#define OFF_W1T  2596                // 128*76 = 9728 words (bf16x2)
#define OFF_W2T  (OFF_W1T + 9728)    // 128*68 = 8704
#define OFF_XS   (OFF_W2T + 8704)    // 4*32*76 = 9728
#define OFF_HS   (OFF_XS + 9728)     // 4*32*68 = 8704
#define SMEM_WORDS (OFF_HS + 8704)
#define SMEM_BYTES (SMEM_WORDS * 4)

__device__ __forceinline__ float silu_f(float v) {
    return v * (1.0f / (1.0f + __expf(-v)));
}

// pack two floats into bf16x2 word: low half = lo, high half = hi
__device__ __forceinline__ unsigned pkbf(float lo, float hi) {
    unsigned r;
    asm("cvt.rn.bf16x2.f32 %0, %1, %2;" : "=r"(r) : "f"(hi), "f"(lo));
    return r;
}

__device__ __forceinline__ void mma_bf16(float d[4],
                                         unsigned a0, unsigned a1,
                                         unsigned a2, unsigned a3,
                                         unsigned b0, unsigned b1) {
    asm volatile(
        "mma.sync.aligned.m16n8k16.row.col.f32.bf16.bf16.f32 "
        "{%0,%1,%2,%3}, {%4,%5,%6,%7}, {%8,%9}, {%0,%1,%2,%3};\n"
        : "+f"(d[0]), "+f"(d[1]), "+f"(d[2]), "+f"(d[3])
        : "r"(a0), "r"(a1), "r"(a2), "r"(a3), "r"(b0), "r"(b1));
}

extern __shared__ unsigned usm[];

__global__ __launch_bounds__(512, 1)
void msg_kernel(const float* __restrict__ point_feat,
                const float* __restrict__ point_xyz,
                const float* __restrict__ sup_xyz,
                const int*   __restrict__ nidx,
                const void*  __restrict__ nmask,
                const float* __restrict__ init_feat,
                const float* __restrict__ task_emb,
                const float* __restrict__ W1, const float* __restrict__ b1,
                const float* __restrict__ W2, const float* __restrict__ b2,
                const float* __restrict__ Wf, const float* __restrict__ bf,
                const float* __restrict__ ln_g, const float* __restrict__ ln_b,
                float* __restrict__ out)
{
    float*    film = (float*)(usm + OFF_FILM);
    float*    part = (float*)(usm + OFF_PART);
    float*    redm = (float*)(usm + OFF_RED);
    int*      flag = (int*)(usm + OFF_FLAG);
    unsigned* W1t  = usm + OFF_W1T;
    unsigned* W2t  = usm + OFF_W2T;
    unsigned* xs   = usm + OFF_XS;
    unsigned* hs   = usm + OFF_HS;

    const int tid = threadIdx.x;

    // ---- prologue: mask dtype detect ----
    if (tid == 0) *flag = 0;
    __syncthreads();
    {
        bool big = false;
        const unsigned* mw = (const unsigned*)nmask;
        for (int i = tid; i < 2048; i += 512)
            if (mw[i] > 1u) big = true;
        if (big) atomicOr(flag, 1);
    }

    // ---- prologue: FiLM table [8][256] ----
    for (int p = 0; p < 4; ++p) {
        const int bb = p * 2 + (tid >> 8);
        const int j  = tid & 255;
        float acc = bf[j];
        const float* te = task_emb + bb * DD;
#pragma unroll 8
        for (int d = 0; d < DD; ++d)
            acc += te[d] * Wf[d * (2 * DD) + j];
        film[bb * 256 + j] = acc;
    }

    // ---- prologue: stage W1^T, W2^T as bf16x2 (k pairs in word) ----
    for (int i = tid; i < DD * STRW1; i += 512) {
        int col = i % DD, kw = i / DD;           // kw 0..75
        int k0 = 2 * kw, k1 = 2 * kw + 1;
        float v0 = (k0 < IC) ? W1[k0 * DD + col] : 0.f;
        float v1 = (k1 < IC) ? W1[k1 * DD + col] : 0.f;
        W1t[col * STRW1 + kw] = pkbf(v0, v1);
    }
    for (int i = tid; i < DD * STRW2; i += 512) {
        int col = i % DD, kw = i / DD;           // kw 0..67
        int k0 = 2 * kw, k1 = 2 * kw + 1;
        float v0 = (k0 < DD) ? W2[k0 * DD + col] : 0.f;
        float v1 = (k1 < DD) ? W2[k1 * DD + col] : 0.f;
        W2t[col * STRW2 + kw] = pkbf(v0, v1);
    }
    // zero xs pad words (66..75 of each row) once; zero hs once
    for (int i = tid; i < 4 * KK * 10; i += 512) {
        int row = i / 10, pw = 66 + i % 10;
        xs[row * STRX + pw] = 0u;
    }
    for (int i = tid; i < 4 * KK * STRH; i += 512) hs[i] = 0u;
    __syncthreads();

    const int mask_u8 = *flag;
    const int w    = tid >> 5;
    const int lane = tid & 31;
    const int g    = lane >> 2;
    const int q    = lane & 3;
    const int su   = w >> 2;             // supernode slot 0..3
    const int wn   = w & 3;              // n32 block
    const int barid = su + 1;

    unsigned* xsu = xs + su * KK * STRX;
    unsigned* hsu = hs + su * KK * STRH;
    float*    psu = part + su * DD;
    float*    rsu = redm + su * 8;

    // per-thread biases for cols c0 = wn*32 + t*8 + 2q, c0+1
    float bi1[4][2], bi2[4][2];
#pragma unroll
    for (int t = 0; t < 4; ++t) {
        int c0 = wn * 32 + t * 8 + 2 * q;
        bi1[t][0] = b1[c0]; bi1[t][1] = b1[c0 + 1];
        bi2[t][0] = b2[c0]; bi2[t][1] = b2[c0 + 1];
    }

    const int niter = (BB * MM) / 4;     // 4096

    for (int iter = blockIdx.x; iter < niter; iter += gridDim.x) {
        const int s = iter * 4 + su;
        const int b = s >> 11;           // s / MM

        // ---- per-warp compact: ballot over mask ----
        const long kbase = (long)s * KK + lane;
        const int nid_k = nidx[kbase];
        bool mk;
        if (mask_u8) mk = ((const uint8_t*)nmask)[kbase] != 0;
        else         mk = ((const int*)nmask)[kbase] != 0;
        const unsigned bal = __ballot_sync(0xffffffffu, mk);
        const int V = __popc(bal);

        // ---- gather rows r = wn*8 .. wn*8+7 ----
        {
            const float sx = sup_xyz[s * 3 + 0];
            const float sy = sup_xyz[s * 3 + 1];
            const float sz = sup_xyz[s * 3 + 2];
            const float* pf = point_feat + (size_t)b * NN * DD;
            const float* px = point_xyz  + (size_t)b * NN * 3;
#pragma unroll
            for (int rr = 0; rr < 8; ++rr) {
                const int r = wn * 8 + rr;
                const bool valid = r < V;
                const unsigned src = valid ? __fns(bal, 0, r + 1) : 0u;
                const int nid = __shfl_sync(0xffffffffu, nid_k, src);
                unsigned w0 = 0u, w1 = 0u;
                if (valid) {
                    float4 f = *(const float4*)(pf + (size_t)nid * DD + 4 * lane);
                    w0 = pkbf(f.x, f.y);
                    w1 = pkbf(f.z, f.w);
                }
                *(uint2*)(xsu + r * STRX + 2 * lane) = make_uint2(w0, w1);
                if (lane == 0) {
                    float rx = 0.f, ryv = 0.f, rz = 0.f, dd = 0.f;
                    if (valid) {
                        rx  = px[nid * 3 + 0] - sx;
                        ryv = px[nid * 3 + 1] - sy;
                        rz  = px[nid * 3 + 2] - sz;
                        dd  = sqrtf(rx * rx + ryv * ryv + rz * rz);
                    }
                    *(uint2*)(xsu + r * STRX + 64) =
                        make_uint2(pkbf(rx, ryv), pkbf(rz, dd));
                }
            }
        }
        asm volatile("bar.sync %0, %1;" :: "r"(barid), "r"(128) : "memory");

        const bool do1 = (V > 16);       // m-tile 1 (rows 16..31) needed?

        // ---- GEMM1: hidden = silu(x @ W1 + b1) ----
        float acc0[4][4], acc1[4][4];
#pragma unroll
        for (int t = 0; t < 4; ++t) {
            acc0[t][0] = bi1[t][0]; acc0[t][1] = bi1[t][1];
            acc0[t][2] = bi1[t][0]; acc0[t][3] = bi1[t][1];
            acc1[t][0] = bi1[t][0]; acc1[t][1] = bi1[t][1];
            acc1[t][2] = bi1[t][0]; acc1[t][3] = bi1[t][1];
        }
        {
            const unsigned* xa = xsu + g * STRX + q;
            const unsigned* xb = xa + 16 * STRX;
            const unsigned* wp = W1t + (wn * 32 + g) * STRW1 + q;
#pragma unroll
            for (int kk = 0; kk < 9; ++kk) {
                unsigned bf0[4], bf1[4];
#pragma unroll
                for (int t = 0; t < 4; ++t) {
                    bf0[t] = wp[t * 8 * STRW1 + kk * 8];
                    bf1[t] = wp[t * 8 * STRW1 + kk * 8 + 4];
                }
                unsigned a0 = xa[kk * 8];
                unsigned a1 = xa[8 * STRX + kk * 8];
                unsigned a2 = xa[kk * 8 + 4];
                unsigned a3 = xa[8 * STRX + kk * 8 + 4];
#pragma unroll
                for (int t = 0; t < 4; ++t)
                    mma_bf16(acc0[t], a0, a1, a2, a3, bf0[t], bf1[t]);
                if (do1) {
                    unsigned c0 = xb[kk * 8];
                    unsigned c1 = xb[8 * STRX + kk * 8];
                    unsigned c2 = xb[kk * 8 + 4];
                    unsigned c3 = xb[8 * STRX + kk * 8 + 4];
#pragma unroll
                    for (int t = 0; t < 4; ++t)
                        mma_bf16(acc1[t], c0, c1, c2, c3, bf0[t], bf1[t]);
                }
            }
        }
        // silu + pack + store hidden
#pragma unroll
        for (int t = 0; t < 4; ++t) {
            const int wrd = wn * 16 + t * 4 + q;
            hsu[(g)     * STRH + wrd] = pkbf(silu_f(acc0[t][0]), silu_f(acc0[t][1]));
            hsu[(g + 8) * STRH + wrd] = pkbf(silu_f(acc0[t][2]), silu_f(acc0[t][3]));
            if (do1) {
                hsu[(16 + g) * STRH + wrd] = pkbf(silu_f(acc1[t][0]), silu_f(acc1[t][1]));
                hsu[(24 + g) * STRH + wrd] = pkbf(silu_f(acc1[t][2]), silu_f(acc1[t][3]));
            }
        }
        asm volatile("bar.sync %0, %1;" :: "r"(barid), "r"(128) : "memory");

        // ---- GEMM2: msg = hidden @ W2 + b2 ----
#pragma unroll
        for (int t = 0; t < 4; ++t) {
            acc0[t][0] = bi2[t][0]; acc0[t][1] = bi2[t][1];
            acc0[t][2] = bi2[t][0]; acc0[t][3] = bi2[t][1];
            acc1[t][0] = bi2[t][0]; acc1[t][1] = bi2[t][1];
            acc1[t][2] = bi2[t][0]; acc1[t][3] = bi2[t][1];
        }
        {
            const unsigned* ha = hsu + g * STRH + q;
            const unsigned* hb = ha + 16 * STRH;
            const unsigned* wp = W2t + (wn * 32 + g) * STRW2 + q;
#pragma unroll
            for (int kk = 0; kk < 8; ++kk) {
                unsigned bf0[4], bf1[4];
#pragma unroll
                for (int t = 0; t < 4; ++t) {
                    bf0[t] = wp[t * 8 * STRW2 + kk * 8];
                    bf1[t] = wp[t * 8 * STRW2 + kk * 8 + 4];
                }
                unsigned a0 = ha[kk * 8];
                unsigned a1 = ha[8 * STRH + kk * 8];
                unsigned a2 = ha[kk * 8 + 4];
                unsigned a3 = ha[8 * STRH + kk * 8 + 4];
#pragma unroll
                for (int t = 0; t < 4; ++t)
                    mma_bf16(acc0[t], a0, a1, a2, a3, bf0[t], bf1[t]);
                if (do1) {
                    unsigned c0 = hb[kk * 8];
                    unsigned c1 = hb[8 * STRH + kk * 8];
                    unsigned c2 = hb[kk * 8 + 4];
                    unsigned c3 = hb[8 * STRH + kk * 8 + 4];
#pragma unroll
                    for (int t = 0; t < 4; ++t)
                        mma_bf16(acc1[t], c0, c1, c2, c3, bf0[t], bf1[t]);
                }
            }
        }
        // ---- masked row sums + warp reduce ----
        {
            const bool v0 = (g)      < V;
            const bool v1 = (g + 8)  < V;
            const bool v2 = (g + 16) < V;
            const bool v3 = (g + 24) < V;
            float sums[4][2];
#pragma unroll
            for (int t = 0; t < 4; ++t) {
                float s0 = (v0 ? acc0[t][0] : 0.f) + (v1 ? acc0[t][2] : 0.f);
                float s1 = (v0 ? acc0[t][1] : 0.f) + (v1 ? acc0[t][3] : 0.f);
                if (do1) {
                    s0 += (v2 ? acc1[t][0] : 0.f) + (v3 ? acc1[t][2] : 0.f);
                    s1 += (v2 ? acc1[t][1] : 0.f) + (v3 ? acc1[t][3] : 0.f);
                }
                sums[t][0] = s0; sums[t][1] = s1;
            }
#pragma unroll
            for (int t = 0; t < 4; ++t) {
#pragma unroll
                for (int off = 4; off <= 16; off <<= 1) {
                    sums[t][0] += __shfl_xor_sync(0xffffffffu, sums[t][0], off);
                    sums[t][1] += __shfl_xor_sync(0xffffffffu, sums[t][1], off);
                }
            }
            if (lane < 4) {
#pragma unroll
                for (int t = 0; t < 4; ++t)
                    *(float2*)(psu + wn * 32 + t * 8 + 2 * q) =
                        make_float2(sums[t][0], sums[t][1]);
            }
        }
        asm volatile("bar.sync %0, %1;" :: "r"(barid), "r"(128) : "memory");

        // ---- epilogue: mean, FiLM, residual, LayerNorm (128 thr/supernode) ----
        {
            const int c = tid & 127;
            const float inv = 1.0f / fmaxf((float)V, 1.0f);
            float agg = psu[c] * inv;
            const float gmm = film[b * 256 + c];
            const float bta = film[b * 256 + 128 + c];
            agg = agg * (1.0f + gmm) + bta;
            const float h = init_feat[(size_t)s * DD + c] + agg;
            float sum = h, sq = h * h;
#pragma unroll
            for (int off = 16; off; off >>= 1) {
                sum += __shfl_xor_sync(0xffffffffu, sum, off);
                sq  += __shfl_xor_sync(0xffffffffu, sq,  off);
            }
            if (lane == 0) {
                rsu[wn * 2 + 0] = sum;
                rsu[wn * 2 + 1] = sq;
            }
            asm volatile("bar.sync %0, %1;" :: "r"(barid), "r"(128) : "memory");
            float sm = 0.f, sqs = 0.f;
#pragma unroll
            for (int ww = 0; ww < 4; ++ww) {
                sm  += rsu[ww * 2 + 0];
                sqs += rsu[ww * 2 + 1];
            }
            const float mu  = sm * (1.0f / DD);
            const float var = sqs * (1.0f / DD) - mu * mu;
            const float y = (h - mu) * rsqrtf(var + EPSV) * ln_g[c] + ln_b[c];
            out[(size_t)s * DD + c] = y;
        }
        // protect xs/part/red before next iteration
        asm volatile("bar.sync %0, %1;" :: "r"(barid), "r"(128) : "memory");
    }
}

// ---------------------------------------------------------------------------
extern "C" void kernel_launch(void* const* d_in, const int* in_sizes, int n_in,
                              void* d_out, int out_size) {
    const float*   point_feat = (const float*)d_in[0];
    const float*   point_xyz  = (const float*)d_in[1];
    const float*   sup_xyz    = (const float*)d_in[2];
    const int*     nidx       = (const int*)d_in[3];
    const void*    nmask      = d_in[4];
    const float*   init_feat  = (const float*)d_in[5];
    const float*   task_emb   = (const float*)d_in[6];
    const float*   W1 = (const float*)d_in[7];
    const float*   b1 = (const float*)d_in[8];
    const float*   W2 = (const float*)d_in[9];
    const float*   b2 = (const float*)d_in[10];
    const float*   Wf = (const float*)d_in[11];
    const float*   bf = (const float*)d_in[12];
    const float*   lng = (const float*)d_in[13];
    const float*   lnb = (const float*)d_in[14];
    float* out = (float*)d_out;

    cudaFuncSetAttribute(msg_kernel, cudaFuncAttributeMaxDynamicSharedMemorySize,
                         SMEM_BYTES);
    int sms = 148;
    cudaDeviceGetAttribute(&sms, cudaDevAttrMultiProcessorCount, 0);

    msg_kernel<<<sms, 512, SMEM_BYTES>>>(point_feat, point_xyz, sup_xyz,
                                         nidx, nmask, init_feat, task_emb,
                                         W1, b1, W2, b2, Wf, bf, lng, lnb, out);
}

// round 7
// speedup vs baseline: 2.3022x; 1.0038x over previous
#include <cuda_runtime.h>
#include <cuda_bf16.h>
#include <stdint.h>
#include <math.h>

// Problem constants
#define BB 8
#define NN 100000
#define MM 2048
#define KK 32
#define DD 128
#define IC 132
#define EPSV 1e-5f

// word strides (32-bit words; each word = 2 bf16 along K)
#define STRX 76      // xs row stride: banks r*12%32 -> conflict-free ldmatrix
#define STRH 68      // hs row stride: banks r*4%32
#define STRW1 76
#define STRW2 68

// SMEM word-offset layout
#define OFF_FILM 0                   // 2048
#define OFF_PART 2048                // 512
#define OFF_RED  2560                // 32
#define OFF_FLAG 2592                // 4
#define OFF_W1T  2596                // 9728
#define OFF_W2T  12324               // 8704
#define OFF_XS   21028               // 2 buf * 4 su * 32 * 76 = 19456
#define OFF_HS   40484               // 4 * 32 * 68 = 8704
#define SMEM_WORDS 49188
#define SMEM_BYTES (SMEM_WORDS * 4)

#define XS_BUF_W 9728                // words per xs buffer
#define XS_SU_W  2432                // words per supernode block in xs
#define HS_SU_W  2176

__device__ __forceinline__ float silu_f(float v) {
    return v * (1.0f / (1.0f + __expf(-v)));
}

__device__ __forceinline__ unsigned pkbf(float lo, float hi) {
    unsigned r;
    asm("cvt.rn.bf16x2.f32 %0, %1, %2;" : "=r"(r) : "f"(hi), "f"(lo));
    return r;
}

__device__ __forceinline__ void mma_bf16(float d[4],
                                         unsigned a0, unsigned a1,
                                         unsigned a2, unsigned a3,
                                         unsigned b0, unsigned b1) {
    asm volatile(
        "mma.sync.aligned.m16n8k16.row.col.f32.bf16.bf16.f32 "
        "{%0,%1,%2,%3}, {%4,%5,%6,%7}, {%8,%9}, {%0,%1,%2,%3};\n"
        : "+f"(d[0]), "+f"(d[1]), "+f"(d[2]), "+f"(d[3])
        : "r"(a0), "r"(a1), "r"(a2), "r"(a3), "r"(b0), "r"(b1));
}

__device__ __forceinline__ void ldsm4(unsigned& r0, unsigned& r1,
                                      unsigned& r2, unsigned& r3, unsigned a) {
    asm volatile("ldmatrix.sync.aligned.m8n8.x4.shared.b16 {%0,%1,%2,%3}, [%4];"
                 : "=r"(r0), "=r"(r1), "=r"(r2), "=r"(r3) : "r"(a));
}

extern __shared__ unsigned usm[];

// gather 8 rows (wn*8..wn*8+7) of x for supernode s into xsn
__device__ __forceinline__ void do_gather(unsigned* xsn, unsigned bal, int V,
                                          int nid_k, int s, int b,
                                          int lane, int wn,
                                          const float* __restrict__ point_feat,
                                          const float* __restrict__ point_xyz,
                                          const float* __restrict__ sup_xyz)
{
    const float sx = sup_xyz[s * 3 + 0];
    const float sy = sup_xyz[s * 3 + 1];
    const float sz = sup_xyz[s * 3 + 2];
    const float* pf = point_feat + (size_t)b * NN * DD;
    const float* px = point_xyz  + (size_t)b * NN * 3;
#pragma unroll
    for (int rr = 0; rr < 8; ++rr) {
        const int r = wn * 8 + rr;
        const bool valid = r < V;
        const unsigned src = valid ? __fns(bal, 0, r + 1) : 0u;
        const int nid = __shfl_sync(0xffffffffu, nid_k, src);
        unsigned w0 = 0u, w1 = 0u;
        if (valid) {
            float4 f = *(const float4*)(pf + (size_t)nid * DD + 4 * lane);
            w0 = pkbf(f.x, f.y);
            w1 = pkbf(f.z, f.w);
        }
        *(uint2*)(xsn + r * STRX + 2 * lane) = make_uint2(w0, w1);
        if (lane == 0) {
            float rx = 0.f, ryv = 0.f, rz = 0.f, dd = 0.f;
            if (valid) {
                rx  = px[nid * 3 + 0] - sx;
                ryv = px[nid * 3 + 1] - sy;
                rz  = px[nid * 3 + 2] - sz;
                dd  = sqrtf(rx * rx + ryv * ryv + rz * rz);
            }
            *(uint2*)(xsn + r * STRX + 64) = make_uint2(pkbf(rx, ryv), pkbf(rz, dd));
        }
    }
}

__global__ __launch_bounds__(512, 1)
void msg_kernel(const float* __restrict__ point_feat,
                const float* __restrict__ point_xyz,
                const float* __restrict__ sup_xyz,
                const int*   __restrict__ nidx,
                const void*  __restrict__ nmask,
                const float* __restrict__ init_feat,
                const float* __restrict__ task_emb,
                const float* __restrict__ W1, const float* __restrict__ b1,
                const float* __restrict__ W2, const float* __restrict__ b2,
                const float* __restrict__ Wf, const float* __restrict__ bf,
                const float* __restrict__ ln_g, const float* __restrict__ ln_b,
                float* __restrict__ out)
{
    float*    film = (float*)(usm + OFF_FILM);
    float*    part = (float*)(usm + OFF_PART);
    float*    redm = (float*)(usm + OFF_RED);
    int*      flag = (int*)(usm + OFF_FLAG);
    unsigned* W1t  = usm + OFF_W1T;
    unsigned* W2t  = usm + OFF_W2T;
    unsigned* xs   = usm + OFF_XS;
    unsigned* hs   = usm + OFF_HS;

    const int tid = threadIdx.x;

    // ---- prologue: mask dtype detect ----
    if (tid == 0) *flag = 0;
    __syncthreads();
    {
        bool big = false;
        const unsigned* mw = (const unsigned*)nmask;
        for (int i = tid; i < 2048; i += 512)
            if (mw[i] > 1u) big = true;
        if (big) atomicOr(flag, 1);
    }

    // ---- prologue: FiLM table [8][256] ----
    for (int p = 0; p < 4; ++p) {
        const int bb = p * 2 + (tid >> 8);
        const int j  = tid & 255;
        float acc = bf[j];
        const float* te = task_emb + bb * DD;
#pragma unroll 8
        for (int d = 0; d < DD; ++d)
            acc += te[d] * Wf[d * (2 * DD) + j];
        film[bb * 256 + j] = acc;
    }

    // ---- prologue: stage W1^T, W2^T as bf16x2 ----
    for (int i = tid; i < DD * STRW1; i += 512) {
        int col = i % DD, kw = i / DD;
        int k0 = 2 * kw, k1 = 2 * kw + 1;
        float v0 = (k0 < IC) ? W1[k0 * DD + col] : 0.f;
        float v1 = (k1 < IC) ? W1[k1 * DD + col] : 0.f;
        W1t[col * STRW1 + kw] = pkbf(v0, v1);
    }
    for (int i = tid; i < DD * STRW2; i += 512) {
        int col = i % DD, kw = i / DD;
        int k0 = 2 * kw, k1 = 2 * kw + 1;
        float v0 = (k0 < DD) ? W2[k0 * DD + col] : 0.f;
        float v1 = (k1 < DD) ? W2[k1 * DD + col] : 0.f;
        W2t[col * STRW2 + kw] = pkbf(v0, v1);
    }
    // zero xs pad words 66..75 in both buffers, zero hs
    for (int i = tid; i < 2 * 128 * 10; i += 512) {
        int buf = i / 1280, rem = i % 1280;
        int row = rem / 10, pw = 66 + rem % 10;
        xs[buf * XS_BUF_W + row * STRX + pw] = 0u;
    }
    for (int i = tid; i < 4 * KK * STRH; i += 512) hs[i] = 0u;

    const int w    = tid >> 5;
    const int lane = tid & 31;
    const int q    = lane & 3;
    const int su   = w >> 2;
    const int wn   = w & 3;
    const int barid = su + 1;

    unsigned* hsu = hs + su * HS_SU_W;
    float*    psu = part + su * DD;
    float*    rsu = redm + su * 8;

    // ldmatrix lane addressing
    unsigned sbase;
    asm("{ .reg .u64 t; cvta.to.shared.u64 t, %1; cvt.u32.u64 %0, t; }"
        : "=r"(sbase) : "l"(usm));
    const int rowA = lane & 15, halfA = lane >> 4;
    const int rB = lane & 7, tB = (lane >> 4) & 1, hB = (lane >> 3) & 1;
    unsigned axc[2];
    axc[0] = sbase + 4u * (OFF_XS + su * XS_SU_W + rowA * STRX + halfA * 4);
    axc[1] = axc[0] + 4u * XS_BUF_W;
    const unsigned ahA = sbase + 4u * (OFF_HS + su * HS_SU_W + rowA * STRH + halfA * 4);
    const unsigned awB1 = sbase + 4u * (OFF_W1T + (wn * 32 + tB * 8 + rB) * STRW1 + hB * 4);
    const unsigned awB2 = sbase + 4u * (OFF_W2T + (wn * 32 + tB * 8 + rB) * STRW2 + hB * 4);

    // per-thread biases
    float bi1[4][2], bi2[4][2];
#pragma unroll
    for (int t = 0; t < 4; ++t) {
        int c0 = wn * 32 + t * 8 + 2 * q;
        bi1[t][0] = b1[c0]; bi1[t][1] = b1[c0 + 1];
        bi2[t][0] = b2[c0]; bi2[t][1] = b2[c0 + 1];
    }

    __syncthreads();
    const int mask_u8 = *flag;

    const int niter  = (BB * MM) / 4;     // 4096
    const int stride = gridDim.x;

    int iter = blockIdx.x;
    int buf = 0;
    unsigned bal_cur = 0; int V_cur = 0;

    // ---- initial gather into buffer 0 ----
    if (iter < niter) {
        const int s0 = iter * 4 + su;
        const long kb = (long)s0 * KK + lane;
        const int nk = nidx[kb];
        bool mk;
        if (mask_u8) mk = ((const uint8_t*)nmask)[kb] != 0;
        else         mk = ((const int*)nmask)[kb] != 0;
        bal_cur = __ballot_sync(0xffffffffu, mk);
        V_cur = __popc(bal_cur);
        do_gather(xs + su * XS_SU_W, bal_cur, V_cur, nk, s0, s0 >> 11,
                  lane, wn, point_feat, point_xyz, sup_xyz);
    }
    __syncthreads();

    for (; iter < niter; iter += stride) {
        const int s = iter * 4 + su;
        const int b = s >> 11;
        const int itn = iter + stride;
        const bool have_nx = itn < niter;

        // prefetch next iteration's indices + mask (latency hidden by GEMM1)
        int nid_nx = 0; bool mk_nx = false;
        if (have_nx) {
            const long kb = (long)(itn * 4 + su) * KK + lane;
            nid_nx = nidx[kb];
            if (mask_u8) mk_nx = ((const uint8_t*)nmask)[kb] != 0;
            else         mk_nx = ((const int*)nmask)[kb] != 0;
        }

        const bool do1 = (V_cur > 16);
        float acc0[4][4], acc1[4][4];

        // ---- GEMM1: hidden = silu(x @ W1 + b1) ----
#pragma unroll
        for (int t = 0; t < 4; ++t) {
            acc0[t][0] = bi1[t][0]; acc0[t][1] = bi1[t][1];
            acc0[t][2] = bi1[t][0]; acc0[t][3] = bi1[t][1];
            acc1[t][0] = bi1[t][0]; acc1[t][1] = bi1[t][1];
            acc1[t][2] = bi1[t][0]; acc1[t][3] = bi1[t][1];
        }
        {
            unsigned axA = axc[buf];
            unsigned aw  = awB1;
#pragma unroll
            for (int kk = 0; kk < 9; ++kk) {
                unsigned B0,B1,B2,B3,B4,B5,B6,B7;
                ldsm4(B0, B1, B2, B3, aw);
                ldsm4(B4, B5, B6, B7, aw + 4864u);   // +16*STRW1*4
                unsigned A0,A1,A2,A3;
                ldsm4(A0, A1, A2, A3, axA);
                mma_bf16(acc0[0], A0, A1, A2, A3, B0, B1);
                mma_bf16(acc0[1], A0, A1, A2, A3, B2, B3);
                mma_bf16(acc0[2], A0, A1, A2, A3, B4, B5);
                mma_bf16(acc0[3], A0, A1, A2, A3, B6, B7);
                if (do1) {
                    unsigned C0,C1,C2,C3;
                    ldsm4(C0, C1, C2, C3, axA + 4864u);  // +16*STRX*4
                    mma_bf16(acc1[0], C0, C1, C2, C3, B0, B1);
                    mma_bf16(acc1[1], C0, C1, C2, C3, B2, B3);
                    mma_bf16(acc1[2], C0, C1, C2, C3, B4, B5);
                    mma_bf16(acc1[3], C0, C1, C2, C3, B6, B7);
                }
                axA += 32u; aw += 32u;
            }
        }
        // silu + pack + store hidden
        {
            const int g = lane >> 2;
#pragma unroll
            for (int t = 0; t < 4; ++t) {
                const int wrd = wn * 16 + t * 4 + q;
                hsu[(g)     * STRH + wrd] = pkbf(silu_f(acc0[t][0]), silu_f(acc0[t][1]));
                hsu[(g + 8) * STRH + wrd] = pkbf(silu_f(acc0[t][2]), silu_f(acc0[t][3]));
                if (do1) {
                    hsu[(16 + g) * STRH + wrd] = pkbf(silu_f(acc1[t][0]), silu_f(acc1[t][1]));
                    hsu[(24 + g) * STRH + wrd] = pkbf(silu_f(acc1[t][2]), silu_f(acc1[t][3]));
                }
            }
        }
        asm volatile("bar.sync %0, %1;" :: "r"(barid), "r"(128) : "memory");

        // ---- gather iter+1 into other buffer (overlaps GEMM2 latency) ----
        unsigned bal_nx = 0; int V_nx = 0;
        if (have_nx) {
            bal_nx = __ballot_sync(0xffffffffu, mk_nx);
            V_nx = __popc(bal_nx);
            const int sn = itn * 4 + su;
            do_gather(xs + (buf ^ 1) * XS_BUF_W + su * XS_SU_W, bal_nx, V_nx,
                      nid_nx, sn, sn >> 11, lane, wn,
                      point_feat, point_xyz, sup_xyz);
        }

        // ---- GEMM2: msg = hidden @ W2 + b2 ----
#pragma unroll
        for (int t = 0; t < 4; ++t) {
            acc0[t][0] = bi2[t][0]; acc0[t][1] = bi2[t][1];
            acc0[t][2] = bi2[t][0]; acc0[t][3] = bi2[t][1];
            acc1[t][0] = bi2[t][0]; acc1[t][1] = bi2[t][1];
            acc1[t][2] = bi2[t][0]; acc1[t][3] = bi2[t][1];
        }
        {
            unsigned axA = ahA;
            unsigned aw  = awB2;
#pragma unroll
            for (int kk = 0; kk < 8; ++kk) {
                unsigned B0,B1,B2,B3,B4,B5,B6,B7;
                ldsm4(B0, B1, B2, B3, aw);
                ldsm4(B4, B5, B6, B7, aw + 4352u);   // +16*STRW2*4
                unsigned A0,A1,A2,A3;
                ldsm4(A0, A1, A2, A3, axA);
                mma_bf16(acc0[0], A0, A1, A2, A3, B0, B1);
                mma_bf16(acc0[1], A0, A1, A2, A3, B2, B3);
                mma_bf16(acc0[2], A0, A1, A2, A3, B4, B5);
                mma_bf16(acc0[3], A0, A1, A2, A3, B6, B7);
                if (do1) {
                    unsigned C0,C1,C2,C3;
                    ldsm4(C0, C1, C2, C3, axA + 4352u);  // +16*STRH*4
                    mma_bf16(acc1[0], C0, C1, C2, C3, B0, B1);
                    mma_bf16(acc1[1], C0, C1, C2, C3, B2, B3);
                    mma_bf16(acc1[2], C0, C1, C2, C3, B4, B5);
                    mma_bf16(acc1[3], C0, C1, C2, C3, B6, B7);
                }
                axA += 32u; aw += 32u;
            }
        }

        // ---- masked row sums + warp reduce ----
        {
            const int g = lane >> 2;
            const bool v0 = (g)      < V_cur;
            const bool v1 = (g + 8)  < V_cur;
            const bool v2 = (g + 16) < V_cur;
            const bool v3 = (g + 24) < V_cur;
            float sums[4][2];
#pragma unroll
            for (int t = 0; t < 4; ++t) {
                float s0 = (v0 ? acc0[t][0] : 0.f) + (v1 ? acc0[t][2] : 0.f);
                float s1 = (v0 ? acc0[t][1] : 0.f) + (v1 ? acc0[t][3] : 0.f);
                if (do1) {
                    s0 += (v2 ? acc1[t][0] : 0.f) + (v3 ? acc1[t][2] : 0.f);
                    s1 += (v2 ? acc1[t][1] : 0.f) + (v3 ? acc1[t][3] : 0.f);
                }
                sums[t][0] = s0; sums[t][1] = s1;
            }
#pragma unroll
            for (int t = 0; t < 4; ++t) {
#pragma unroll
                for (int off = 4; off <= 16; off <<= 1) {
                    sums[t][0] += __shfl_xor_sync(0xffffffffu, sums[t][0], off);
                    sums[t][1] += __shfl_xor_sync(0xffffffffu, sums[t][1], off);
                }
            }
            if (lane < 4) {
#pragma unroll
                for (int t = 0; t < 4; ++t)
                    *(float2*)(psu + wn * 32 + t * 8 + 2 * q) =
                        make_float2(sums[t][0], sums[t][1]);
            }
        }
        asm volatile("bar.sync %0, %1;" :: "r"(barid), "r"(128) : "memory");

        // ---- epilogue: mean, FiLM, residual, LayerNorm ----
        {
            const int c = tid & 127;
            const float inv = 1.0f / fmaxf((float)V_cur, 1.0f);
            float agg = psu[c] * inv;
            const float gmm = film[b * 256 + c];
            const float bta = film[b * 256 + 128 + c];
            agg = agg * (1.0f + gmm) + bta;
            const float h = init_feat[(size_t)s * DD + c] + agg;
            float sum = h, sq = h * h;
#pragma unroll
            for (int off = 16; off; off >>= 1) {
                sum += __shfl_xor_sync(0xffffffffu, sum, off);
                sq  += __shfl_xor_sync(0xffffffffu, sq,  off);
            }
            if (lane == 0) {
                rsu[wn * 2 + 0] = sum;
                rsu[wn * 2 + 1] = sq;
            }
            asm volatile("bar.sync %0, %1;" :: "r"(barid), "r"(128) : "memory");
            float sm = 0.f, sqs = 0.f;
#pragma unroll
            for (int ww = 0; ww < 4; ++ww) {
                sm  += rsu[ww * 2 + 0];
                sqs += rsu[ww * 2 + 1];
            }
            const float mu  = sm * (1.0f / DD);
            const float var = sqs * (1.0f / DD) - mu * mu;
            const float y = (h - mu) * rsqrtf(var + EPSV) * ln_g[c] + ln_b[c];
            out[(size_t)s * DD + c] = y;
        }

        // rotate: next iteration's data already gathered
        bal_cur = bal_nx; V_cur = V_nx;
        buf ^= 1;
    }
}

// ---------------------------------------------------------------------------
extern "C" void kernel_launch(void* const* d_in, const int* in_sizes, int n_in,
                              void* d_out, int out_size) {
    const float*   point_feat = (const float*)d_in[0];
    const float*   point_xyz  = (const float*)d_in[1];
    const float*   sup_xyz    = (const float*)d_in[2];
    const int*     nidx       = (const int*)d_in[3];
    const void*    nmask      = d_in[4];
    const float*   init_feat  = (const float*)d_in[5];
    const float*   task_emb   = (const float*)d_in[6];
    const float*   W1 = (const float*)d_in[7];
    const float*   b1 = (const float*)d_in[8];
    const float*   W2 = (const float*)d_in[9];
    const float*   b2 = (const float*)d_in[10];
    const float*   Wf = (const float*)d_in[11];
    const float*   bf = (const float*)d_in[12];
    const float*   lng = (const float*)d_in[13];
    const float*   lnb = (const float*)d_in[14];
    float* out = (float*)d_out;

    cudaFuncSetAttribute(msg_kernel, cudaFuncAttributeMaxDynamicSharedMemorySize,
                         SMEM_BYTES);
    int sms = 148;
    cudaDeviceGetAttribute(&sms, cudaDevAttrMultiProcessorCount, 0);

    msg_kernel<<<sms, 512, SMEM_BYTES>>>(point_feat, point_xyz, sup_xyz,
                                         nidx, nmask, init_feat, task_emb,
                                         W1, b1, W2, b2, Wf, bf, lng, lnb, out);
}

// round 9
// speedup vs baseline: 3.0824x; 1.3389x over previous
#include <cuda_runtime.h>
#include <cuda_bf16.h>
#include <stdint.h>
#include <math.h>

// Problem constants
#define BB 8
#define NN 100000
#define MM 2048
#define KK 32
#define DD 128
#define IC 132
#define EPSV 1e-5f

// word strides (32-bit words; each word = 2 bf16 along K). Row strides are
// multiples of 4 words (16B) as required by ldmatrix; bank patterns validated R5-R7.
#define STRX 76
#define STRW1 76
#define STRW2 68

// smem word-offset layout
#define XS_W   0                 // 16 warps * 32 rows * 76 words = 38912
#define W1T_W  38912             // 128 * 76 = 9728
#define W2T_W  48640             // 128 * 68 = 8704
#define B1_W   57344             // 128
#define B2_W   57472             // 128
#define LNG_W  57600             // 128
#define LNB_W  57728             // 128
#define FLAG_W 57856             // 4
#define SMEM_WORDS 57860
#define SMEM_BYTES (SMEM_WORDS * 4)   // 231,440 B  (< 232,448 cap)

#define XS_WARP_W 2432           // 32 * 76

// FiLM table lives in device global (L2-hot, 8KB) to fit smem budget
__device__ float g_film[BB * 2 * DD];

__device__ __forceinline__ float silu_f(float v) {
    return v * (1.0f / (1.0f + __expf(-v)));
}
__device__ __forceinline__ unsigned pkbf(float lo, float hi) {
    unsigned r;
    asm("cvt.rn.bf16x2.f32 %0, %1, %2;" : "=r"(r) : "f"(hi), "f"(lo));
    return r;
}
__device__ __forceinline__ void mma_bf16(float d[4],
                                         unsigned a0, unsigned a1,
                                         unsigned a2, unsigned a3,
                                         unsigned b0, unsigned b1) {
    asm volatile(
        "mma.sync.aligned.m16n8k16.row.col.f32.bf16.bf16.f32 "
        "{%0,%1,%2,%3}, {%4,%5,%6,%7}, {%8,%9}, {%0,%1,%2,%3};\n"
        : "+f"(d[0]), "+f"(d[1]), "+f"(d[2]), "+f"(d[3])
        : "r"(a0), "r"(a1), "r"(a2), "r"(a3), "r"(b0), "r"(b1));
}
__device__ __forceinline__ void ldsm4(unsigned& r0, unsigned& r1,
                                      unsigned& r2, unsigned& r3, unsigned a) {
    asm volatile("ldmatrix.sync.aligned.m8n8.x4.shared.b16 {%0,%1,%2,%3}, [%4];"
                 : "=r"(r0), "=r"(r1), "=r"(r2), "=r"(r3) : "r"(a));
}
__device__ __forceinline__ unsigned smem_u32(const void* p) {
    unsigned a;
    asm("{ .reg .u64 t; cvta.to.shared.u64 t, %1; cvt.u32.u64 %0, t; }"
        : "=r"(a) : "l"(p));
    return a;
}

extern __shared__ unsigned usm[];

__global__ __launch_bounds__(512, 1)
void msg_kernel(const float* __restrict__ point_feat,
                const float* __restrict__ point_xyz,
                const float* __restrict__ sup_xyz,
                const int*   __restrict__ nidx,
                const void*  __restrict__ nmask,
                const float* __restrict__ init_feat,
                const float* __restrict__ task_emb,
                const float* __restrict__ W1, const float* __restrict__ b1,
                const float* __restrict__ W2, const float* __restrict__ b2,
                const float* __restrict__ Wf, const float* __restrict__ bf,
                const float* __restrict__ ln_g, const float* __restrict__ ln_b,
                float* __restrict__ out)
{
    float* b1s  = (float*)(usm + B1_W);
    float* b2s  = (float*)(usm + B2_W);
    float* lngs = (float*)(usm + LNG_W);
    float* lnbs = (float*)(usm + LNB_W);
    int*   flag = (int*)(usm + FLAG_W);

    const int tid = threadIdx.x;

    // ---- prologue: mask dtype detect ----
    if (tid == 0) *flag = 0;
    __syncthreads();
    {
        bool big = false;
        const unsigned* mw = (const unsigned*)nmask;
        for (int i = tid; i < 2048; i += 512)
            if (mw[i] > 1u) big = true;
        if (big) atomicOr(flag, 1);
    }
    // ---- FiLM table -> device global (all CTAs write identical values) ----
    for (int p = 0; p < 4; ++p) {
        const int bb = p * 2 + (tid >> 8);
        const int j  = tid & 255;
        float acc = bf[j];
        const float* te = task_emb + bb * DD;
#pragma unroll 8
        for (int d = 0; d < DD; ++d)
            acc += te[d] * Wf[d * (2 * DD) + j];
        g_film[bb * 256 + j] = acc;
    }
    // ---- stage W1^T (128 n x 76 kw; zero pad k>=132) ----
    for (int i = tid; i < DD * STRW1; i += 512) {
        int col = i % DD, kw = i / DD;
        int k0 = 2 * kw, k1 = 2 * kw + 1;
        float v0 = (k0 < IC) ? W1[k0 * DD + col] : 0.f;
        float v1 = (k1 < IC) ? W1[k1 * DD + col] : 0.f;
        usm[W1T_W + col * STRW1 + kw] = pkbf(v0, v1);
    }
    // ---- stage W2^T (128 n x 68 kw) ----
    for (int i = tid; i < DD * STRW2; i += 512) {
        int col = i % DD, kw = i / DD;
        int k0 = 2 * kw, k1 = 2 * kw + 1;
        float v0 = (k0 < DD) ? W2[k0 * DD + col] : 0.f;
        float v1 = (k1 < DD) ? W2[k1 * DD + col] : 0.f;
        usm[W2T_W + col * STRW2 + kw] = pkbf(v0, v1);
    }
    // ---- zero xs pad words 66..71 of every row (k 132..143 padding) ----
    for (int i = tid; i < 16 * 32 * 6; i += 512) {
        int w_ = i / 192, rem = i % 192;
        int row = rem / 6, pw = 66 + rem % 6;
        usm[XS_W + w_ * XS_WARP_W + row * STRX + pw] = 0u;
    }
    // ---- small vectors ----
    for (int i = tid; i < DD; i += 512) {
        b1s[i] = b1[i]; b2s[i] = b2[i]; lngs[i] = ln_g[i]; lnbs[i] = ln_b[i];
    }
    __syncthreads();
    const int mask_u8 = *flag;

    const int wid  = tid >> 5;
    const int lane = tid & 31;
    const int q    = lane & 3;
    const int g    = lane >> 2;

    unsigned* xsw = usm + XS_W + wid * XS_WARP_W;

    const unsigned sbase = smem_u32(usm);
    const int rowA = lane & 15, halfA = lane >> 4;
    const unsigned axA0 = sbase + 4u * (XS_W + wid * XS_WARP_W + rowA * STRX + halfA * 4);
    const int rB = lane & 7, tB = (lane >> 4) & 1, hB = (lane >> 3) & 1;
    const unsigned awB1 = sbase + 4u * (W1T_W + (tB * 8 + rB) * STRW1 + hB * 4);
    const unsigned awB2 = sbase + 4u * (W2T_W + (tB * 8 + rB) * STRW2 + hB * 4);

    const int sstep = gridDim.x * 16;

    for (int s = blockIdx.x * 16 + wid; s < BB * MM; s += sstep) {
        const int b = s >> 11;

        // ---- compact: ballot over this supernode's mask ----
        const size_t kb = (size_t)s * KK + lane;
        const int nid_k = nidx[kb];
        bool mk;
        if (mask_u8) mk = ((const uint8_t*)nmask)[kb] != 0;
        else         mk = ((const int*)nmask)[kb] != 0;
        const unsigned bal = __ballot_sync(0xffffffffu, mk);
        const int V = __popc(bal);

        // ---- gather V rows of x = [feat | rel,dist] into warp-private xs ----
        {
            const float sx = sup_xyz[s * 3 + 0];
            const float sy = sup_xyz[s * 3 + 1];
            const float sz = sup_xyz[s * 3 + 2];
            const float* pf = point_feat + (size_t)b * NN * DD;
            const float* px = point_xyz  + (size_t)b * NN * 3;
            for (int r = 0; r < V; ++r) {
                const unsigned src = __fns(bal, 0, r + 1);
                const int nid = __shfl_sync(0xffffffffu, nid_k, src);
                float4 f = *(const float4*)(pf + (size_t)nid * DD + 4 * lane);
                *(uint2*)(xsw + r * STRX + 2 * lane) =
                    make_uint2(pkbf(f.x, f.y), pkbf(f.z, f.w));
                if (lane == 0) {
                    float rx  = px[nid * 3 + 0] - sx;
                    float ryv = px[nid * 3 + 1] - sy;
                    float rz  = px[nid * 3 + 2] - sz;
                    float dd  = sqrtf(rx * rx + ryv * ryv + rz * rz);
                    *(uint2*)(xsw + r * STRX + 64) =
                        make_uint2(pkbf(rx, ryv), pkbf(rz, dd));
                }
            }
        }
        __syncwarp();

        // ---- per m16-tile: GEMM1 (regs) -> silu/pack -> GEMM2 (A from regs) ----
        const int ntl = (V > 16) ? 2 : 1;
        for (int tl = 0; tl < ntl; ++tl) {
            unsigned hp[4][4][2];
            const unsigned axbase = axA0 + (unsigned)tl * 4864u;  // +16*STRX*4

            // GEMM1: 4 n32-blocks x 9 k16-chunks
#pragma unroll
            for (int nb = 0; nb < 4; ++nb) {
                float acc[4][4];
#pragma unroll
                for (int t = 0; t < 4; ++t)
                    acc[t][0] = acc[t][1] = acc[t][2] = acc[t][3] = 0.f;
                unsigned aA = axbase;
                unsigned aB = awB1 + nb * 9728u;                  // +32*STRW1*4
#pragma unroll
                for (int kk = 0; kk < 9; ++kk) {
                    unsigned A0, A1, A2, A3, B0, B1, B2, B3, B4, B5, B6, B7;
                    ldsm4(A0, A1, A2, A3, aA);
                    ldsm4(B0, B1, B2, B3, aB);
                    ldsm4(B4, B5, B6, B7, aB + 4864u);            // +16*STRW1*4
                    mma_bf16(acc[0], A0, A1, A2, A3, B0, B1);
                    mma_bf16(acc[1], A0, A1, A2, A3, B2, B3);
                    mma_bf16(acc[2], A0, A1, A2, A3, B4, B5);
                    mma_bf16(acc[3], A0, A1, A2, A3, B6, B7);
                    aA += 32u; aB += 32u;
                }
                // bias + silu + pack -> A-fragments of GEMM2 (register renaming)
#pragma unroll
                for (int t = 0; t < 4; ++t) {
                    float2 bv = *(const float2*)(b1s + nb * 32 + t * 8 + 2 * q);
                    hp[nb][t][0] = pkbf(silu_f(acc[t][0] + bv.x),
                                        silu_f(acc[t][1] + bv.y));
                    hp[nb][t][1] = pkbf(silu_f(acc[t][2] + bv.x),
                                        silu_f(acc[t][3] + bv.y));
                }
            }

            // GEMM2: A comes straight from hp registers
            const bool v0 = (tl * 16 + g)     < V;
            const bool v1 = (tl * 16 + g + 8) < V;
            for (int nb2 = 0; nb2 < 4; ++nb2) {
                float facc[4][4];
#pragma unroll
                for (int t = 0; t < 4; ++t)
                    facc[t][0] = facc[t][1] = facc[t][2] = facc[t][3] = 0.f;
                unsigned aB = awB2 + nb2 * 8704u;                 // +32*STRW2*4
#pragma unroll
                for (int kk = 0; kk < 8; ++kk) {
                    unsigned B0, B1, B2, B3, B4, B5, B6, B7;
                    ldsm4(B0, B1, B2, B3, aB);
                    ldsm4(B4, B5, B6, B7, aB + 4352u);            // +16*STRW2*4
                    const unsigned a0 = hp[kk >> 1][2 * (kk & 1)][0];
                    const unsigned a1 = hp[kk >> 1][2 * (kk & 1)][1];
                    const unsigned a2 = hp[kk >> 1][2 * (kk & 1) + 1][0];
                    const unsigned a3 = hp[kk >> 1][2 * (kk & 1) + 1][1];
                    mma_bf16(facc[0], a0, a1, a2, a3, B0, B1);
                    mma_bf16(facc[1], a0, a1, a2, a3, B2, B3);
                    mma_bf16(facc[2], a0, a1, a2, a3, B4, B5);
                    mma_bf16(facc[3], a0, a1, a2, a3, B6, B7);
                    aB += 32u;
                }
                // masked row sums + reduce over g-lanes
                float sums[4][2];
#pragma unroll
                for (int t = 0; t < 4; ++t) {
                    sums[t][0] = (v0 ? facc[t][0] : 0.f) + (v1 ? facc[t][2] : 0.f);
                    sums[t][1] = (v0 ? facc[t][1] : 0.f) + (v1 ? facc[t][3] : 0.f);
                }
#pragma unroll
                for (int t = 0; t < 4; ++t) {
#pragma unroll
                    for (int off = 4; off <= 16; off <<= 1) {
                        sums[t][0] += __shfl_xor_sync(0xffffffffu, sums[t][0], off);
                        sums[t][1] += __shfl_xor_sync(0xffffffffu, sums[t][1], off);
                    }
                }
                if (lane < 4) {
#pragma unroll
                    for (int t = 0; t < 4; ++t) {
                        const int c = nb2 * 32 + t * 8 + 2 * q;
                        float2* p = (float2*)(xsw + (c >> 2) * STRX + 72 + (c & 3));
                        if (tl == 0) {
                            *p = make_float2(sums[t][0], sums[t][1]);
                        } else {
                            float2 o = *p;
                            *p = make_float2(o.x + sums[t][0], o.y + sums[t][1]);
                        }
                    }
                }
            }
        }
        __syncwarp();

        // ---- epilogue: mean(+V*b2), FiLM, residual, LayerNorm (4 ch/lane) ----
        {
            float4 msg = *(float4*)(xsw + lane * STRX + 72);
            const float Vf = (float)V;
            const float invV = 1.0f / fmaxf(Vf, 1.0f);
            float4 b2v = *(const float4*)(b2s + 4 * lane);
            float4 gm  = *(const float4*)(g_film + b * 256 + 4 * lane);
            float4 bt  = *(const float4*)(g_film + b * 256 + 128 + 4 * lane);
            float4 fi  = *(const float4*)(init_feat + (size_t)s * DD + 4 * lane);
            float h0 = fi.x + ((msg.x + Vf * b2v.x) * invV) * (1.0f + gm.x) + bt.x;
            float h1 = fi.y + ((msg.y + Vf * b2v.y) * invV) * (1.0f + gm.y) + bt.y;
            float h2 = fi.z + ((msg.z + Vf * b2v.z) * invV) * (1.0f + gm.z) + bt.z;
            float h3 = fi.w + ((msg.w + Vf * b2v.w) * invV) * (1.0f + gm.w) + bt.w;
            float sum = h0 + h1 + h2 + h3;
            float sq  = h0 * h0 + h1 * h1 + h2 * h2 + h3 * h3;
#pragma unroll
            for (int off = 16; off; off >>= 1) {
                sum += __shfl_xor_sync(0xffffffffu, sum, off);
                sq  += __shfl_xor_sync(0xffffffffu, sq,  off);
            }
            const float mu  = sum * (1.0f / DD);
            const float var = sq * (1.0f / DD) - mu * mu;
            const float rs  = rsqrtf(var + EPSV);
            float4 lg = *(const float4*)(lngs + 4 * lane);
            float4 lb = *(const float4*)(lnbs + 4 * lane);
            float4 y;
            y.x = (h0 - mu) * rs * lg.x + lb.x;
            y.y = (h1 - mu) * rs * lg.y + lb.y;
            y.z = (h2 - mu) * rs * lg.z + lb.z;
            y.w = (h3 - mu) * rs * lg.w + lb.w;
            *(float4*)(out + (size_t)s * DD + 4 * lane) = y;
        }
    }
}

// ---------------------------------------------------------------------------
extern "C" void kernel_launch(void* const* d_in, const int* in_sizes, int n_in,
                              void* d_out, int out_size) {
    const float*   point_feat = (const float*)d_in[0];
    const float*   point_xyz  = (const float*)d_in[1];
    const float*   sup_xyz    = (const float*)d_in[2];
    const int*     nidx       = (const int*)d_in[3];
    const void*    nmask      = d_in[4];
    const float*   init_feat  = (const float*)d_in[5];
    const float*   task_emb   = (const float*)d_in[6];
    const float*   W1 = (const float*)d_in[7];
    const float*   b1 = (const float*)d_in[8];
    const float*   W2 = (const float*)d_in[9];
    const float*   b2 = (const float*)d_in[10];
    const float*   Wf = (const float*)d_in[11];
    const float*   bf = (const float*)d_in[12];
    const float*   lng = (const float*)d_in[13];
    const float*   lnb = (const float*)d_in[14];
    float* out = (float*)d_out;

    cudaFuncSetAttribute(msg_kernel, cudaFuncAttributeMaxDynamicSharedMemorySize,
                         SMEM_BYTES);
    int sms = 148;
    cudaDeviceGetAttribute(&sms, cudaDevAttrMultiProcessorCount, 0);

    msg_kernel<<<sms, 512, SMEM_BYTES>>>(point_feat, point_xyz, sup_xyz,
                                         nidx, nmask, init_feat, task_emb,
                                         W1, b1, W2, b2, Wf, bf, lng, lnb, out);
}

// round 10
// speedup vs baseline: 4.0725x; 1.3212x over previous
#include <cuda_runtime.h>
#include <cuda_bf16.h>
#include <stdint.h>
#include <math.h>

// Problem constants
#define BB 8
#define NN 100000
#define MM 2048
#define KK 32
#define DD 128
#define IC 132
#define EPSV 1e-5f

// word strides (32-bit words; each word = 2 bf16 along K)
#define STRX 76
#define STRW1 76
#define STRW2 68

// smem word-offset layout
#define XS_W   0                 // 16 warps * 32 rows * 76 words = 38912
#define W1T_W  38912             // 128 * 76 = 9728
#define W2T_W  48640             // 128 * 68 = 8704
#define B1_W   57344             // 128
#define B2_W   57472             // 128
#define LNG_W  57600             // 128
#define LNB_W  57728             // 128
#define FLAG_W 57856             // 4
#define SMEM_WORDS 57860
#define SMEM_BYTES (SMEM_WORDS * 4)   // 231,440 B

#define XS_WARP_W 2432           // 32 * 76

// FiLM table in device global (L2-hot)
__device__ float g_film[BB * 2 * DD];

__device__ __forceinline__ float silu_f(float v) {
    return v * (1.0f / (1.0f + __expf(-v)));
}
__device__ __forceinline__ unsigned pkbf(float lo, float hi) {
    unsigned r;
    asm("cvt.rn.bf16x2.f32 %0, %1, %2;" : "=r"(r) : "f"(hi), "f"(lo));
    return r;
}
__device__ __forceinline__ void mma_bf16(float d[4],
                                         unsigned a0, unsigned a1,
                                         unsigned a2, unsigned a3,
                                         unsigned b0, unsigned b1) {
    asm volatile(
        "mma.sync.aligned.m16n8k16.row.col.f32.bf16.bf16.f32 "
        "{%0,%1,%2,%3}, {%4,%5,%6,%7}, {%8,%9}, {%0,%1,%2,%3};\n"
        : "+f"(d[0]), "+f"(d[1]), "+f"(d[2]), "+f"(d[3])
        : "r"(a0), "r"(a1), "r"(a2), "r"(a3), "r"(b0), "r"(b1));
}
__device__ __forceinline__ void ldsm4(unsigned& r0, unsigned& r1,
                                      unsigned& r2, unsigned& r3, unsigned a) {
    asm volatile("ldmatrix.sync.aligned.m8n8.x4.shared.b16 {%0,%1,%2,%3}, [%4];"
                 : "=r"(r0), "=r"(r1), "=r"(r2), "=r"(r3) : "r"(a));
}
__device__ __forceinline__ unsigned smem_u32(const void* p) {
    unsigned a;
    asm("{ .reg .u64 t; cvta.to.shared.u64 t, %1; cvt.u32.u64 %0, t; }"
        : "=r"(a) : "l"(p));
    return a;
}

extern __shared__ unsigned usm[];

__global__ __launch_bounds__(512, 1)
void msg_kernel(const float* __restrict__ point_feat,
                const float* __restrict__ point_xyz,
                const float* __restrict__ sup_xyz,
                const int*   __restrict__ nidx,
                const void*  __restrict__ nmask,
                const float* __restrict__ init_feat,
                const float* __restrict__ task_emb,
                const float* __restrict__ W1, const float* __restrict__ b1,
                const float* __restrict__ W2, const float* __restrict__ b2,
                const float* __restrict__ Wf, const float* __restrict__ bf,
                const float* __restrict__ ln_g, const float* __restrict__ ln_b,
                float* __restrict__ out)
{
    float* b1s  = (float*)(usm + B1_W);
    float* b2s  = (float*)(usm + B2_W);
    float* lngs = (float*)(usm + LNG_W);
    float* lnbs = (float*)(usm + LNB_W);
    int*   flag = (int*)(usm + FLAG_W);

    const int tid = threadIdx.x;

    // ---- prologue: mask dtype detect ----
    if (tid == 0) *flag = 0;
    __syncthreads();
    {
        bool big = false;
        const unsigned* mw = (const unsigned*)nmask;
        for (int i = tid; i < 2048; i += 512)
            if (mw[i] > 1u) big = true;
        if (big) atomicOr(flag, 1);
    }
    // ---- FiLM table -> device global ----
    for (int p = 0; p < 4; ++p) {
        const int bb = p * 2 + (tid >> 8);
        const int j  = tid & 255;
        float acc = bf[j];
        const float* te = task_emb + bb * DD;
#pragma unroll 8
        for (int d = 0; d < DD; ++d)
            acc += te[d] * Wf[d * (2 * DD) + j];
        g_film[bb * 256 + j] = acc;
    }
    // ---- stage W1^T ----
    for (int i = tid; i < DD * STRW1; i += 512) {
        int col = i % DD, kw = i / DD;
        int k0 = 2 * kw, k1 = 2 * kw + 1;
        float v0 = (k0 < IC) ? W1[k0 * DD + col] : 0.f;
        float v1 = (k1 < IC) ? W1[k1 * DD + col] : 0.f;
        usm[W1T_W + col * STRW1 + kw] = pkbf(v0, v1);
    }
    // ---- stage W2^T ----
    for (int i = tid; i < DD * STRW2; i += 512) {
        int col = i % DD, kw = i / DD;
        int k0 = 2 * kw, k1 = 2 * kw + 1;
        float v0 = (k0 < DD) ? W2[k0 * DD + col] : 0.f;
        float v1 = (k1 < DD) ? W2[k1 * DD + col] : 0.f;
        usm[W2T_W + col * STRW2 + kw] = pkbf(v0, v1);
    }
    // ---- zero xs pad words 66..71 (k 132..143) ----
    for (int i = tid; i < 16 * 32 * 6; i += 512) {
        int w_ = i / 192, rem = i % 192;
        int row = rem / 6, pw = 66 + rem % 6;
        usm[XS_W + w_ * XS_WARP_W + row * STRX + pw] = 0u;
    }
    // ---- small vectors ----
    for (int i = tid; i < DD; i += 512) {
        b1s[i] = b1[i]; b2s[i] = b2[i]; lngs[i] = ln_g[i]; lnbs[i] = ln_b[i];
    }
    __syncthreads();
    const int mask_u8 = *flag;

    const int wid  = tid >> 5;
    const int lane = tid & 31;
    const int q    = lane & 3;
    const int g    = lane >> 2;

    unsigned* xsw = usm + XS_W + wid * XS_WARP_W;

    const unsigned sbase = smem_u32(usm);
    const int rowA = lane & 15, halfA = lane >> 4;
    const unsigned axA0 = sbase + 4u * (XS_W + wid * XS_WARP_W + rowA * STRX + halfA * 4);
    const int rB = lane & 7, tB = (lane >> 4) & 1, hB = (lane >> 3) & 1;
    const unsigned awB1 = sbase + 4u * (W1T_W + (tB * 8 + rB) * STRW1 + hB * 4);
    const unsigned awB2 = sbase + 4u * (W2T_W + (tB * 8 + rB) * STRW2 + hB * 4);

    const int sstep = gridDim.x * 16;

    for (int s = blockIdx.x * 16 + wid; s < BB * MM; s += sstep) {
        const int b = s >> 11;

        // ---- compact: ballot over this supernode's mask ----
        const size_t kb = (size_t)s * KK + lane;
        const int nid_k = nidx[kb];
        bool mk;
        if (mask_u8) mk = ((const uint8_t*)nmask)[kb] != 0;
        else         mk = ((const int*)nmask)[kb] != 0;
        const unsigned bal = __ballot_sync(0xffffffffu, mk);
        const int V = __popc(bal);

        const float* pf = point_feat + (size_t)b * NN * DD;

        // ---- xyz phase: lane r handles row r (parallel across lanes) ----
        {
            const unsigned srcx = (lane < V) ? __fns(bal, 0, lane + 1) : 0u;
            const int nidx_l = __shfl_sync(0xffffffffu, nid_k, srcx);
            if (lane < V) {
                const float* px = point_xyz + (size_t)b * NN * 3;
                float rx  = px[nidx_l * 3 + 0] - sup_xyz[s * 3 + 0];
                float ryv = px[nidx_l * 3 + 1] - sup_xyz[s * 3 + 1];
                float rz  = px[nidx_l * 3 + 2] - sup_xyz[s * 3 + 2];
                float dd  = sqrtf(rx * rx + ryv * ryv + rz * rz);
                *(uint2*)(xsw + lane * STRX + 64) =
                    make_uint2(pkbf(rx, ryv), pkbf(rz, dd));
            }
        }

        // ---- feature gather: batches of 8 rows, MLP=8 ----
#pragma unroll
        for (int b8 = 0; b8 < 4; ++b8) {
            const int r0 = b8 * 8;
            if (r0 >= V) break;
            float4 f[8];
#pragma unroll
            for (int j = 0; j < 8; ++j) {
                const int r = r0 + j;
                const bool val = r < V;
                const unsigned src = val ? __fns(bal, 0, r + 1) : 0u;
                const int nid = __shfl_sync(0xffffffffu, nid_k, src);
                if (val)
                    f[j] = *(const float4*)(pf + (size_t)nid * DD + 4 * lane);
            }
#pragma unroll
            for (int j = 0; j < 8; ++j) {
                const int r = r0 + j;
                if (r < V)
                    *(uint2*)(xsw + r * STRX + 2 * lane) =
                        make_uint2(pkbf(f[j].x, f[j].y), pkbf(f[j].z, f[j].w));
            }
        }
        __syncwarp();

        // ---- per m16-tile: GEMM1 (regs) -> silu/pack -> GEMM2 (A from regs) ----
        const int ntl = (V > 16) ? 2 : 1;
        for (int tl = 0; tl < ntl; ++tl) {
            unsigned hp[4][4][2];
            const unsigned axbase = axA0 + (unsigned)tl * 4864u;  // +16*STRX*4

            // GEMM1: 4 n32-blocks x 9 k16-chunks
#pragma unroll
            for (int nb = 0; nb < 4; ++nb) {
                float acc[4][4];
#pragma unroll
                for (int t = 0; t < 4; ++t)
                    acc[t][0] = acc[t][1] = acc[t][2] = acc[t][3] = 0.f;
                unsigned aA = axbase;
                unsigned aB = awB1 + nb * 9728u;                  // +32*STRW1*4
#pragma unroll
                for (int kk = 0; kk < 9; ++kk) {
                    unsigned A0, A1, A2, A3, B0, B1, B2, B3, B4, B5, B6, B7;
                    ldsm4(A0, A1, A2, A3, aA);
                    ldsm4(B0, B1, B2, B3, aB);
                    ldsm4(B4, B5, B6, B7, aB + 4864u);            // +16*STRW1*4
                    mma_bf16(acc[0], A0, A1, A2, A3, B0, B1);
                    mma_bf16(acc[1], A0, A1, A2, A3, B2, B3);
                    mma_bf16(acc[2], A0, A1, A2, A3, B4, B5);
                    mma_bf16(acc[3], A0, A1, A2, A3, B6, B7);
                    aA += 32u; aB += 32u;
                }
                // bias + silu + pack -> GEMM2 A-fragments (register renaming)
#pragma unroll
                for (int t = 0; t < 4; ++t) {
                    float2 bv = *(const float2*)(b1s + nb * 32 + t * 8 + 2 * q);
                    hp[nb][t][0] = pkbf(silu_f(acc[t][0] + bv.x),
                                        silu_f(acc[t][1] + bv.y));
                    hp[nb][t][1] = pkbf(silu_f(acc[t][2] + bv.x),
                                        silu_f(acc[t][3] + bv.y));
                }
            }

            // GEMM2: A straight from hp registers
            const bool v0 = (tl * 16 + g)     < V;
            const bool v1 = (tl * 16 + g + 8) < V;
            for (int nb2 = 0; nb2 < 4; ++nb2) {
                float facc[4][4];
#pragma unroll
                for (int t = 0; t < 4; ++t)
                    facc[t][0] = facc[t][1] = facc[t][2] = facc[t][3] = 0.f;
                unsigned aB = awB2 + nb2 * 8704u;                 // +32*STRW2*4
#pragma unroll
                for (int kk = 0; kk < 8; ++kk) {
                    unsigned B0, B1, B2, B3, B4, B5, B6, B7;
                    ldsm4(B0, B1, B2, B3, aB);
                    ldsm4(B4, B5, B6, B7, aB + 4352u);            // +16*STRW2*4
                    const unsigned a0 = hp[kk >> 1][2 * (kk & 1)][0];
                    const unsigned a1 = hp[kk >> 1][2 * (kk & 1)][1];
                    const unsigned a2 = hp[kk >> 1][2 * (kk & 1) + 1][0];
                    const unsigned a3 = hp[kk >> 1][2 * (kk & 1) + 1][1];
                    mma_bf16(facc[0], a0, a1, a2, a3, B0, B1);
                    mma_bf16(facc[1], a0, a1, a2, a3, B2, B3);
                    mma_bf16(facc[2], a0, a1, a2, a3, B4, B5);
                    mma_bf16(facc[3], a0, a1, a2, a3, B6, B7);
                    aB += 32u;
                }
                // masked row sums + reduce over g-lanes
                float sums[4][2];
#pragma unroll
                for (int t = 0; t < 4; ++t) {
                    sums[t][0] = (v0 ? facc[t][0] : 0.f) + (v1 ? facc[t][2] : 0.f);
                    sums[t][1] = (v0 ? facc[t][1] : 0.f) + (v1 ? facc[t][3] : 0.f);
                }
#pragma unroll
                for (int t = 0; t < 4; ++t) {
#pragma unroll
                    for (int off = 4; off <= 16; off <<= 1) {
                        sums[t][0] += __shfl_xor_sync(0xffffffffu, sums[t][0], off);
                        sums[t][1] += __shfl_xor_sync(0xffffffffu, sums[t][1], off);
                    }
                }
                if (lane < 4) {
#pragma unroll
                    for (int t = 0; t < 4; ++t) {
                        const int c = nb2 * 32 + t * 8 + 2 * q;
                        float2* p = (float2*)(xsw + (c >> 2) * STRX + 72 + (c & 3));
                        if (tl == 0) {
                            *p = make_float2(sums[t][0], sums[t][1]);
                        } else {
                            float2 o = *p;
                            *p = make_float2(o.x + sums[t][0], o.y + sums[t][1]);
                        }
                    }
                }
            }
        }
        __syncwarp();

        // ---- epilogue: mean(+V*b2), FiLM, residual, LayerNorm ----
        {
            float4 msg = *(float4*)(xsw + lane * STRX + 72);
            const float Vf = (float)V;
            const float invV = 1.0f / fmaxf(Vf, 1.0f);
            float4 b2v = *(const float4*)(b2s + 4 * lane);
            float4 gm  = *(const float4*)(g_film + b * 256 + 4 * lane);
            float4 bt  = *(const float4*)(g_film + b * 256 + 128 + 4 * lane);
            float4 fi  = *(const float4*)(init_feat + (size_t)s * DD + 4 * lane);
            float h0 = fi.x + ((msg.x + Vf * b2v.x) * invV) * (1.0f + gm.x) + bt.x;
            float h1 = fi.y + ((msg.y + Vf * b2v.y) * invV) * (1.0f + gm.y) + bt.y;
            float h2 = fi.z + ((msg.z + Vf * b2v.z) * invV) * (1.0f + gm.z) + bt.z;
            float h3 = fi.w + ((msg.w + Vf * b2v.w) * invV) * (1.0f + gm.w) + bt.w;
            float sum = h0 + h1 + h2 + h3;
            float sq  = h0 * h0 + h1 * h1 + h2 * h2 + h3 * h3;
#pragma unroll
            for (int off = 16; off; off >>= 1) {
                sum += __shfl_xor_sync(0xffffffffu, sum, off);
                sq  += __shfl_xor_sync(0xffffffffu, sq,  off);
            }
            const float mu  = sum * (1.0f / DD);
            const float var = sq * (1.0f / DD) - mu * mu;
            const float rs  = rsqrtf(var + EPSV);
            float4 lg = *(const float4*)(lngs + 4 * lane);
            float4 lb = *(const float4*)(lnbs + 4 * lane);
            float4 y;
            y.x = (h0 - mu) * rs * lg.x + lb.x;
            y.y = (h1 - mu) * rs * lg.y + lb.y;
            y.z = (h2 - mu) * rs * lg.z + lb.z;
            y.w = (h3 - mu) * rs * lg.w + lb.w;
            *(float4*)(out + (size_t)s * DD + 4 * lane) = y;
        }
    }
}

// ---------------------------------------------------------------------------
extern "C" void kernel_launch(void* const* d_in, const int* in_sizes, int n_in,
                              void* d_out, int out_size) {
    const float*   point_feat = (const float*)d_in[0];
    const float*   point_xyz  = (const float*)d_in[1];
    const float*   sup_xyz    = (const float*)d_in[2];
    const int*     nidx       = (const int*)d_in[3];
    const void*    nmask      = d_in[4];
    const float*   init_feat  = (const float*)d_in[5];
    const float*   task_emb   = (const float*)d_in[6];
    const float*   W1 = (const float*)d_in[7];
    const float*   b1 = (const float*)d_in[8];
    const float*   W2 = (const float*)d_in[9];
    const float*   b2 = (const float*)d_in[10];
    const float*   Wf = (const float*)d_in[11];
    const float*   bf = (const float*)d_in[12];
    const float*   lng = (const float*)d_in[13];
    const float*   lnb = (const float*)d_in[14];
    float* out = (float*)d_out;

    cudaFuncSetAttribute(msg_kernel, cudaFuncAttributeMaxDynamicSharedMemorySize,
                         SMEM_BYTES);
    int sms = 148;
    cudaDeviceGetAttribute(&sms, cudaDevAttrMultiProcessorCount, 0);

    msg_kernel<<<sms, 512, SMEM_BYTES>>>(point_feat, point_xyz, sup_xyz,
                                         nidx, nmask, init_feat, task_emb,
                                         W1, b1, W2, b2, Wf, bf, lng, lnb, out);
}